// round 2
// baseline (speedup 1.0000x reference)
#include <cuda_runtime.h>
#include <cstdint>

// ---------------------------------------------------------------------------
// Problem constants
// ---------------------------------------------------------------------------
constexpr int S_LEN  = 2048;
constexpr int HID    = 2048;
constexpr int NH     = 16;
constexpr int QR     = 1536;
constexpr int KVR    = 512;
constexpr int DN     = 128;   // d_nope
constexpr int DR     = 64;    // d_rope
constexpr int DQK    = 192;   // d_nope + d_rope
constexpr int DV     = 128;
constexpr float EPS  = 1e-6f;

// ---------------------------------------------------------------------------
// Scratch (device globals; no allocation allowed)
// ---------------------------------------------------------------------------
__device__ float g_qa  [S_LEN * QR];           // q_a (rmsnorm'ed in place)
__device__ float g_q   [S_LEN * NH * DQK];     // q_b output
__device__ float g_kva [S_LEN * (KVR + DR)];   // kv_a (first 512 rmsnorm'ed in place)
__device__ float g_kvb [S_LEN * NH * (DN + DV)];
__device__ float g_Qf  [NH * S_LEN * DQK];     // per-head Q (rope'd, scaled)
__device__ float g_Kf  [NH * S_LEN * DQK];     // per-head K (rope'd)
__device__ float g_Vf  [NH * S_LEN * DV];      // per-head V
__device__ float g_attn[S_LEN * NH * DV];      // attention output (t, h*DV+d)

// ---------------------------------------------------------------------------
// Generic NT GEMM: C[M,N] = A[M,K(lda)] * B[N,K]^T   (all fp32, row-major)
// 64x64 tile, BK=16, 256 threads, 4x4 micro-tile.
// Requires: M,N % 64 == 0, K % 16 == 0, lda/K multiples of 4.
// ---------------------------------------------------------------------------
__global__ void __launch_bounds__(256) gemm_nt_kernel(
    const float* __restrict__ A, int lda,
    const float* __restrict__ B,
    float* __restrict__ C,
    int M, int N, int K)
{
    __shared__ float As[64][17];
    __shared__ float Bs[64][17];

    const int tid = threadIdx.x;
    const int tx = tid & 15;
    const int ty = tid >> 4;
    const int m0 = blockIdx.y * 64;
    const int n0 = blockIdx.x * 64;

    const int lrow = tid >> 2;         // 0..63
    const int lk   = (tid & 3) * 4;    // 0,4,8,12

    const float* Aptr = A + (size_t)(m0 + lrow) * lda + lk;
    const float* Bptr = B + (size_t)(n0 + lrow) * K   + lk;

    float acc[4][4];
    #pragma unroll
    for (int i = 0; i < 4; i++)
        #pragma unroll
        for (int j = 0; j < 4; j++) acc[i][j] = 0.f;

    for (int kt = 0; kt < K; kt += 16) {
        float4 a4 = *(const float4*)(Aptr + kt);
        float4 b4 = *(const float4*)(Bptr + kt);
        As[lrow][lk + 0] = a4.x; As[lrow][lk + 1] = a4.y;
        As[lrow][lk + 2] = a4.z; As[lrow][lk + 3] = a4.w;
        Bs[lrow][lk + 0] = b4.x; Bs[lrow][lk + 1] = b4.y;
        Bs[lrow][lk + 2] = b4.z; Bs[lrow][lk + 3] = b4.w;
        __syncthreads();

        #pragma unroll
        for (int k = 0; k < 16; k++) {
            float a[4], b[4];
            #pragma unroll
            for (int i = 0; i < 4; i++) a[i] = As[ty + 16 * i][k];
            #pragma unroll
            for (int j = 0; j < 4; j++) b[j] = Bs[tx + 16 * j][k];
            #pragma unroll
            for (int i = 0; i < 4; i++)
                #pragma unroll
                for (int j = 0; j < 4; j++)
                    acc[i][j] = fmaf(a[i], b[j], acc[i][j]);
        }
        __syncthreads();
    }

    #pragma unroll
    for (int i = 0; i < 4; i++)
        #pragma unroll
        for (int j = 0; j < 4; j++)
            C[(size_t)(m0 + ty + 16 * i) * N + (n0 + tx + 16 * j)] = acc[i][j];
}

// ---------------------------------------------------------------------------
// RMSNorm (in place): one block per row, n columns of a row with stride ld
// ---------------------------------------------------------------------------
__global__ void __launch_bounds__(256) rmsnorm_kernel(
    float* __restrict__ x, const float* __restrict__ w, int ld, int n)
{
    const int row = blockIdx.x;
    float* xr = x + (size_t)row * ld;

    float s = 0.f;
    for (int i = threadIdx.x; i < n; i += 256) {
        float v = xr[i];
        s += v * v;
    }
    __shared__ float red[8];
    #pragma unroll
    for (int o = 16; o; o >>= 1) s += __shfl_xor_sync(0xffffffffu, s, o);
    if ((threadIdx.x & 31) == 0) red[threadIdx.x >> 5] = s;
    __syncthreads();
    if (threadIdx.x < 32) {
        float v = (threadIdx.x < 8) ? red[threadIdx.x] : 0.f;
        #pragma unroll
        for (int o = 4; o; o >>= 1) v += __shfl_xor_sync(0xffffffffu, v, o);
        if (threadIdx.x == 0) red[0] = v;
    }
    __syncthreads();
    const float r = rsqrtf(red[0] / (float)n + EPS);
    for (int i = threadIdx.x; i < n; i += 256)
        xr[i] = w[i] * xr[i] * r;
}

// ---------------------------------------------------------------------------
// RoPE + assemble per-head contiguous Q/K/V.
// One block per token t. Softmax scale folded into Q.
//
// position_ids dtype robustness: the reference declares int64 but JAX with
// x64 disabled silently produces int32. Detect at runtime: 32-bit word #1 of
// the buffer is 0 for little-endian int64 (high half of position_ids[0]) and
// position_ids[1] (>=1, nonzero) for int32. All reads stay in bounds for the
// detected dtype.
// ---------------------------------------------------------------------------
__global__ void __launch_bounds__(256) assemble_kernel(
    const void* __restrict__ pos_ids)
{
    const int t = blockIdx.x;
    const int tid = threadIdx.x;

    __shared__ float cs[DR], sn[DR], kr[DR], kx[DR];
    __shared__ float s_pos;

    if (tid == 0) {
        const int* p32 = (const int*)pos_ids;
        long long pv;
        if (p32[1] == 0) {                       // int64 layout
            pv = ((const long long*)pos_ids)[t];
        } else {                                 // int32 layout
            pv = (long long)p32[t];
        }
        s_pos = (float)pv;
    }
    __syncthreads();

    const float pos = s_pos;
    if (tid < DR) {
        const int j = tid & 31;
        // inv_freq = 10000^(-2j/64), computed in fp64 for accuracy
        double e = -((double)(2 * j) / (double)DR) * 13.287712379549449;  // log2(10000)
        float inv = (float)exp2(e);
        float ang = pos * inv;
        cs[tid] = cosf(ang);
        sn[tid] = sinf(ang);
        kx[tid] = g_kva[(size_t)t * (KVR + DR) + KVR + tid];
    }
    __syncthreads();
    if (tid < DR) {
        float v;
        if (tid < 32) v = kx[tid] * cs[tid] - kx[tid + 32] * sn[tid];
        else          v = kx[tid] * cs[tid] + kx[tid - 32] * sn[tid];
        kr[tid] = v;
    }
    __syncthreads();

    const float scale = rsqrtf((float)DQK);

    for (int h = 0; h < NH; h++) {
        const float* qrow  = g_q   + (size_t)t * NH * DQK + h * DQK;
        const float* kvrow = g_kvb + (size_t)t * NH * (DN + DV) + h * (DN + DV);
        float* Qd = g_Qf + ((size_t)h * S_LEN + t) * DQK;
        float* Kd = g_Kf + ((size_t)h * S_LEN + t) * DQK;
        float* Vd = g_Vf + ((size_t)h * S_LEN + t) * DV;

        for (int d = tid; d < DQK; d += 256) {
            float v;
            if (d < DN) v = qrow[d];
            else {
                int i = d - DN;
                float x = qrow[d];
                if (i < 32) v = x * cs[i] - qrow[DN + i + 32] * sn[i];
                else        v = x * cs[i] + qrow[DN + i - 32] * sn[i];
            }
            Qd[d] = v * scale;
        }
        for (int d = tid; d < DQK; d += 256)
            Kd[d] = (d < DN) ? kvrow[d] : kr[d - DN];
        for (int d = tid; d < DV; d += 256)
            Vd[d] = kvrow[DN + d];
    }
}

// ---------------------------------------------------------------------------
// Flash attention (causal), fp32. One block per (64-query tile, head).
// 256 threads (16x16). S: 4x4 micro; O: 4x8 micro.
// ---------------------------------------------------------------------------
constexpr int BQ = 64, BK = 64;
constexpr int QS_STRIDE = 193;   // 193 % 32 == 1 -> conflict-free column reads
constexpr int KS_STRIDE = 193;
constexpr int VS_STRIDE = 129;
constexpr int SS_STRIDE = 65;
constexpr int FLASH_SMEM_FLOATS =
    BQ * QS_STRIDE + BK * KS_STRIDE + BK * VS_STRIDE + BQ * SS_STRIDE + 3 * BQ;
constexpr size_t FLASH_SMEM_BYTES = FLASH_SMEM_FLOATS * sizeof(float);

__global__ void __launch_bounds__(256) flash_kernel()
{
    const int h  = blockIdx.y;
    const int qt = blockIdx.x;
    const int q0 = qt * BQ;
    const int tid = threadIdx.x;
    const int tx = tid & 15;
    const int ty = tid >> 4;

    extern __shared__ float sm[];
    float* Qs   = sm;
    float* Ks   = Qs + BQ * QS_STRIDE;
    float* Vs   = Ks + BK * KS_STRIDE;
    float* Ss   = Vs + BK * VS_STRIDE;
    float* mrow = Ss + BQ * SS_STRIDE;
    float* lrow = mrow + BQ;
    float* arow = lrow + BQ;

    const float* Qg = g_Qf + ((size_t)h * S_LEN + q0) * DQK;
    const float* Kg = g_Kf + (size_t)h * S_LEN * DQK;
    const float* Vg = g_Vf + (size_t)h * S_LEN * DV;

    // load Q tile (64 x 192)
    for (int idx = tid; idx < BQ * (DQK / 4); idx += 256) {
        int r  = idx / (DQK / 4);
        int c4 = (idx % (DQK / 4)) * 4;
        float4 v = *(const float4*)(Qg + (size_t)r * DQK + c4);
        float* dst = Qs + r * QS_STRIDE + c4;
        dst[0] = v.x; dst[1] = v.y; dst[2] = v.z; dst[3] = v.w;
    }
    if (tid < BQ) { mrow[tid] = -1e30f; lrow[tid] = 0.f; }

    float o[4][8];
    #pragma unroll
    for (int i = 0; i < 4; i++)
        #pragma unroll
        for (int c = 0; c < 8; c++) o[i][c] = 0.f;

    __syncthreads();

    const int nkt = qt + 1;   // causal: only tiles <= diagonal
    for (int kt = 0; kt < nkt; kt++) {
        const int k0 = kt * BK;

        // load K tile (64 x 192) and V tile (64 x 128)
        for (int idx = tid; idx < BK * (DQK / 4); idx += 256) {
            int r  = idx / (DQK / 4);
            int c4 = (idx % (DQK / 4)) * 4;
            float4 v = *(const float4*)(Kg + (size_t)(k0 + r) * DQK + c4);
            float* dst = Ks + r * KS_STRIDE + c4;
            dst[0] = v.x; dst[1] = v.y; dst[2] = v.z; dst[3] = v.w;
        }
        for (int idx = tid; idx < BK * (DV / 4); idx += 256) {
            int r  = idx / (DV / 4);
            int c4 = (idx % (DV / 4)) * 4;
            float4 v = *(const float4*)(Vg + (size_t)(k0 + r) * DV + c4);
            float* dst = Vs + r * VS_STRIDE + c4;
            dst[0] = v.x; dst[1] = v.y; dst[2] = v.z; dst[3] = v.w;
        }
        __syncthreads();

        // S = Q K^T  (scale already folded into Q)
        float s[4][4];
        #pragma unroll
        for (int i = 0; i < 4; i++)
            #pragma unroll
            for (int j = 0; j < 4; j++) s[i][j] = 0.f;

        #pragma unroll 4
        for (int d = 0; d < DQK; d++) {
            float a[4], b[4];
            #pragma unroll
            for (int i = 0; i < 4; i++) a[i] = Qs[(ty + 16 * i) * QS_STRIDE + d];
            #pragma unroll
            for (int j = 0; j < 4; j++) b[j] = Ks[(tx + 16 * j) * KS_STRIDE + d];
            #pragma unroll
            for (int i = 0; i < 4; i++)
                #pragma unroll
                for (int j = 0; j < 4; j++)
                    s[i][j] = fmaf(a[i], b[j], s[i][j]);
        }

        // write S (with causal mask on the diagonal tile)
        const bool diag = (kt == qt);
        #pragma unroll
        for (int i = 0; i < 4; i++) {
            int qr = ty + 16 * i;
            #pragma unroll
            for (int j = 0; j < 4; j++) {
                int kc = tx + 16 * j;
                float v = s[i][j];
                if (diag && kc > qr) v = -1e30f;
                Ss[qr * SS_STRIDE + kc] = v;
            }
        }
        __syncthreads();

        // online softmax, one thread per query row
        if (tid < BQ) {
            const int r = tid;
            float* srow = Ss + r * SS_STRIDE;
            float mold = mrow[r];
            float mx = mold;
            #pragma unroll 8
            for (int j = 0; j < BK; j++) mx = fmaxf(mx, srow[j]);
            float alpha = __expf(mold - mx);
            float sum = 0.f;
            #pragma unroll 8
            for (int j = 0; j < BK; j++) {
                float p = __expf(srow[j] - mx);
                srow[j] = p;
                sum += p;
            }
            mrow[r] = mx;
            lrow[r] = lrow[r] * alpha + sum;
            arow[r] = alpha;
        }
        __syncthreads();

        // rescale O, then O += P @ V
        float al[4];
        #pragma unroll
        for (int i = 0; i < 4; i++) al[i] = arow[ty + 16 * i];
        #pragma unroll
        for (int i = 0; i < 4; i++)
            #pragma unroll
            for (int c = 0; c < 8; c++) o[i][c] *= al[i];

        #pragma unroll 4
        for (int j = 0; j < BK; j++) {
            float p[4], v[8];
            #pragma unroll
            for (int i = 0; i < 4; i++) p[i] = Ss[(ty + 16 * i) * SS_STRIDE + j];
            #pragma unroll
            for (int c = 0; c < 8; c++) v[c] = Vs[j * VS_STRIDE + tx + 16 * c];
            #pragma unroll
            for (int i = 0; i < 4; i++)
                #pragma unroll
                for (int c = 0; c < 8; c++)
                    o[i][c] = fmaf(p[i], v[c], o[i][c]);
        }
        __syncthreads();   // protect Ks/Vs/Ss before next tile load
    }

    // epilogue: O /= l, write to attn buffer (t, h*DV + d)
    #pragma unroll
    for (int i = 0; i < 4; i++) {
        const int qr = ty + 16 * i;
        const float inv = __fdividef(1.f, lrow[qr]);
        #pragma unroll
        for (int c = 0; c < 8; c++)
            g_attn[(size_t)(q0 + qr) * (NH * DV) + h * DV + tx + 16 * c] =
                o[i][c] * inv;
    }
}

// ---------------------------------------------------------------------------
// Launch
// ---------------------------------------------------------------------------
extern "C" void kernel_launch(void* const* d_in, const int* in_sizes, int n_in,
                              void* d_out, int out_size)
{
    const float* hs       = (const float*)d_in[0];
    const void*  pos_ids  = d_in[1];
    const float* q_a_w    = (const float*)d_in[2];
    const float* q_a_ln_w = (const float*)d_in[3];
    const float* q_b_w    = (const float*)d_in[4];
    const float* kv_a_w   = (const float*)d_in[5];
    const float* kv_a_ln_w= (const float*)d_in[6];
    const float* kv_b_w   = (const float*)d_in[7];
    const float* o_w      = (const float*)d_in[8];
    float*       out      = (float*)d_out;

    float *p_qa, *p_q, *p_kva, *p_kvb, *p_attn;
    cudaGetSymbolAddress((void**)&p_qa,   g_qa);
    cudaGetSymbolAddress((void**)&p_q,    g_q);
    cudaGetSymbolAddress((void**)&p_kva,  g_kva);
    cudaGetSymbolAddress((void**)&p_kvb,  g_kvb);
    cudaGetSymbolAddress((void**)&p_attn, g_attn);

    cudaFuncSetAttribute(flash_kernel,
                         cudaFuncAttributeMaxDynamicSharedMemorySize,
                         (int)FLASH_SMEM_BYTES);

    // 1. q_a = hs @ q_a_w^T   (2048 x 1536, K=2048)
    gemm_nt_kernel<<<dim3(QR / 64, S_LEN / 64), 256>>>(
        hs, HID, q_a_w, p_qa, S_LEN, QR, HID);

    // 2. rmsnorm(q_a) in place
    rmsnorm_kernel<<<S_LEN, 256>>>(p_qa, q_a_ln_w, QR, QR);

    // 3. q = q_a_n @ q_b_w^T  (2048 x 3072, K=1536)
    gemm_nt_kernel<<<dim3(NH * DQK / 64, S_LEN / 64), 256>>>(
        p_qa, QR, q_b_w, p_q, S_LEN, NH * DQK, QR);

    // 4. kv_a = hs @ kv_a_w^T (2048 x 576, K=2048)
    gemm_nt_kernel<<<dim3((KVR + DR) / 64, S_LEN / 64), 256>>>(
        hs, HID, kv_a_w, p_kva, S_LEN, KVR + DR, HID);

    // 5. rmsnorm(kv_a[:, :512]) in place (row stride 576)
    rmsnorm_kernel<<<S_LEN, 256>>>(p_kva, kv_a_ln_w, KVR + DR, KVR);

    // 6. kv_b = ckv @ kv_b_w^T (2048 x 4096, K=512, lda=576)
    gemm_nt_kernel<<<dim3(NH * (DN + DV) / 64, S_LEN / 64), 256>>>(
        p_kva, KVR + DR, kv_b_w, p_kvb, S_LEN, NH * (DN + DV), KVR);

    // 7. RoPE + assemble per-head Q/K/V
    assemble_kernel<<<S_LEN, 256>>>(pos_ids);

    // 8. causal flash attention
    flash_kernel<<<dim3(S_LEN / BQ, NH), 256, FLASH_SMEM_BYTES>>>();

    // 9. out = attn @ o_w^T (2048 x 2048, K=2048)
    gemm_nt_kernel<<<dim3(HID / 64, S_LEN / 64), 256>>>(
        p_attn, NH * DV, o_w, out, S_LEN, HID, HID);
}

// round 3
// speedup vs baseline: 1.1713x; 1.1713x over previous
#include <cuda_runtime.h>
#include <cstdint>

// ---------------------------------------------------------------------------
// Problem constants
// ---------------------------------------------------------------------------
constexpr int S_LEN  = 2048;
constexpr int HID    = 2048;
constexpr int NH     = 16;
constexpr int QR     = 1536;
constexpr int KVR    = 512;
constexpr int DN     = 128;   // d_nope
constexpr int DR     = 64;    // d_rope
constexpr int DQK    = 192;   // d_nope + d_rope
constexpr int DV     = 128;
constexpr float EPS  = 1e-6f;

// ---------------------------------------------------------------------------
// Scratch (device globals; no allocation allowed)
// ---------------------------------------------------------------------------
__device__ float g_qa  [S_LEN * QR];
__device__ float g_q   [S_LEN * NH * DQK];
__device__ float g_kva [S_LEN * (KVR + DR)];
__device__ float g_kvb [S_LEN * NH * (DN + DV)];
__device__ float g_Qf  [NH * S_LEN * DQK];
__device__ float g_Kf  [NH * S_LEN * DQK];
__device__ float g_Vf  [NH * S_LEN * DV];
__device__ float g_attn[S_LEN * NH * DV];

// ---------------------------------------------------------------------------
// TF32 helpers
// ---------------------------------------------------------------------------
__device__ __forceinline__ uint32_t f2tf32(float x) {
    uint32_t r;
    asm("cvt.rna.tf32.f32 %0, %1;" : "=r"(r) : "f"(x));
    return r;
}

__device__ __forceinline__ void mma_tf32(float* c, const uint4& a, const uint2& b) {
    asm volatile(
        "mma.sync.aligned.m16n8k8.row.col.f32.tf32.tf32.f32 "
        "{%0,%1,%2,%3}, {%4,%5,%6,%7}, {%8,%9}, {%0,%1,%2,%3};"
        : "+f"(c[0]), "+f"(c[1]), "+f"(c[2]), "+f"(c[3])
        : "r"(a.x), "r"(a.y), "r"(a.z), "r"(a.w), "r"(b.x), "r"(b.y));
}

// ---------------------------------------------------------------------------
// 3xTF32 NT GEMM: C[M,N] = A[M,K(lda)] * B[N,K]^T, fp32 in/out.
// CTA tile 128x128, BK=16, 256 threads (8 warps, warp tile 64x32),
// double-buffered smem with fragment-permuted layout, hi/lo TF32 planes.
// Requires: M % 128 == 0, K % 16 == 0. N arbitrary (guards; N % 8 == 0).
//
// Smem (dynamic, 64KB):
//   sA: [stage(2)][plane(2)][2048 floats]   (128 rows x 16 k, permuted)
//   sB: [stage(2)][plane(2)][2048 floats]   (128 n   x 16 k, permuted)
// A slot (m16k8 frag of m-tile mt, k8-tile kt):
//   off = (mt*2+kt)*128 + lane*4 + reg  (reg = (khalf)*2 + (rowhalf))
// B slot (n8k8 frag): off = (nt*2+kt)*64 + lane*2 + reg (reg = khalf)
// ---------------------------------------------------------------------------
constexpr int GEMM_SMEM_BYTES = 2 * 2 * 2048 * 4 * 2;   // 65536

__device__ __forceinline__ void stage_chunk(
    float* __restrict__ sAh, float* __restrict__ sAl,
    float* __restrict__ sBh, float* __restrict__ sBl,
    const float4& a0, const float4& a1,
    const float4& b0, const float4& b1,
    int abase, int s_mbit, int bbase)
{
    float av[8] = {a0.x, a0.y, a0.z, a0.w, a1.x, a1.y, a1.z, a1.w};
    float bv[8] = {b0.x, b0.y, b0.z, b0.w, b1.x, b1.y, b1.z, b1.w};
    #pragma unroll
    for (int e = 0; e < 8; e++) {
        uint32_t ahi = f2tf32(av[e]);
        uint32_t alo = f2tf32(av[e] - __uint_as_float(ahi));
        int aoff = abase + (e & 3) * 4 + (e >> 2) * 2 + s_mbit;
        sAh[aoff] = __uint_as_float(ahi);
        sAl[aoff] = __uint_as_float(alo);

        uint32_t bhi = f2tf32(bv[e]);
        uint32_t blo = f2tf32(bv[e] - __uint_as_float(bhi));
        int boff = bbase + (e & 3) * 2 + (e >> 2);
        sBh[boff] = __uint_as_float(bhi);
        sBl[boff] = __uint_as_float(blo);
    }
}

__global__ void __launch_bounds__(256) gemm_tf32_kernel(
    const float* __restrict__ A, int lda,
    const float* __restrict__ B,
    float* __restrict__ C,
    int N, int K)
{
    extern __shared__ float smg[];
    float* sA = smg;            // 8192 floats
    float* sB = smg + 8192;     // 8192 floats

    const int tid  = threadIdx.x;
    const int lane = tid & 31;
    const int warp = tid >> 5;
    const int wm = warp >> 2;   // 0..1
    const int wn = warp & 3;    // 0..3
    const int m0 = blockIdx.y * 128;
    const int n0 = blockIdx.x * 128;

    // staging coordinates: thread pair (2u, 2u+1) covers row u, k-halves 0/1
    const int srow  = tid >> 1;        // 0..127
    const int kt_st = tid & 1;         // k8 subtile within BK=16
    const int s_mbit = (srow >> 3) & 1;
    const int abase = ((srow >> 4) * 2 + kt_st) * 128 + (srow & 7) * 16;
    const int bbase = ((srow >> 3) * 2 + kt_st) * 64  + (srow & 7) * 8;
    const bool bvalid = (n0 + srow) < N;

    const float* Ag = A + (size_t)(m0 + srow) * lda + kt_st * 8;
    const float* Bg = B + (size_t)(n0 + srow) * K   + kt_st * 8;

    float acc[4][4][4];
    #pragma unroll
    for (int i = 0; i < 4; i++)
        #pragma unroll
        for (int j = 0; j < 4; j++)
            #pragma unroll
            for (int r = 0; r < 4; r++) acc[i][j][r] = 0.f;

    const int nc = K / 16;
    const float4 z4 = make_float4(0.f, 0.f, 0.f, 0.f);

    // prologue: stage chunk 0 into stage 0
    {
        float4 a0 = *(const float4*)(Ag);
        float4 a1 = *(const float4*)(Ag + 4);
        float4 b0 = bvalid ? *(const float4*)(Bg)     : z4;
        float4 b1 = bvalid ? *(const float4*)(Bg + 4) : z4;
        stage_chunk(sA, sA + 2048, sB, sB + 2048, a0, a1, b0, b1,
                    abase, s_mbit, bbase);
    }
    __syncthreads();

    for (int c = 0; c < nc; c++) {
        const int s = c & 1;

        // prefetch next chunk gmem -> regs
        float4 pa0 = z4, pa1 = z4, pb0 = z4, pb1 = z4;
        if (c + 1 < nc) {
            const float* ap = Ag + (c + 1) * 16;
            pa0 = *(const float4*)(ap);
            pa1 = *(const float4*)(ap + 4);
            if (bvalid) {
                const float* bp = Bg + (c + 1) * 16;
                pb0 = *(const float4*)(bp);
                pb1 = *(const float4*)(bp + 4);
            }
        }

        // compute on stage s
        const float* pAh = sA + (s * 2 + 0) * 2048;
        const float* pAl = sA + (s * 2 + 1) * 2048;
        const float* pBh = sB + (s * 2 + 0) * 2048;
        const float* pBl = sB + (s * 2 + 1) * 2048;

        #pragma unroll
        for (int kt = 0; kt < 2; kt++) {
            uint4 Ah[4], Al[4];
            uint2 Bh[4], Bl[4];
            #pragma unroll
            for (int i = 0; i < 4; i++) {
                int off = (((wm * 4 + i) * 2 + kt) * 128) + lane * 4;
                Ah[i] = *(const uint4*)&pAh[off];
                Al[i] = *(const uint4*)&pAl[off];
            }
            #pragma unroll
            for (int j = 0; j < 4; j++) {
                int off = (((wn * 4 + j) * 2 + kt) * 64) + lane * 2;
                Bh[j] = *(const uint2*)&pBh[off];
                Bl[j] = *(const uint2*)&pBl[off];
            }
            #pragma unroll
            for (int i = 0; i < 4; i++)
                #pragma unroll
                for (int j = 0; j < 4; j++) {
                    mma_tf32(acc[i][j], Ah[i], Bh[j]);
                    mma_tf32(acc[i][j], Ah[i], Bl[j]);
                    mma_tf32(acc[i][j], Al[i], Bh[j]);
                }
        }

        // store prefetched chunk into the other stage
        if (c + 1 < nc) {
            const int t = s ^ 1;
            stage_chunk(sA + (t * 2) * 2048, sA + (t * 2 + 1) * 2048,
                        sB + (t * 2) * 2048, sB + (t * 2 + 1) * 2048,
                        pa0, pa1, pb0, pb1, abase, s_mbit, bbase);
        }
        __syncthreads();
    }

    // epilogue
    const int g = lane >> 2;
    const int q = lane & 3;
    #pragma unroll
    for (int i = 0; i < 4; i++) {
        const int row = m0 + wm * 64 + i * 16 + g;
        #pragma unroll
        for (int j = 0; j < 4; j++) {
            const int colb = n0 + wn * 32 + j * 8;
            if (colb < N) {
                const int col = colb + 2 * q;
                *(float2*)&C[(size_t)row * N + col] =
                    make_float2(acc[i][j][0], acc[i][j][1]);
                *(float2*)&C[(size_t)(row + 8) * N + col] =
                    make_float2(acc[i][j][2], acc[i][j][3]);
            }
        }
    }
}

// ---------------------------------------------------------------------------
// RMSNorm (in place)
// ---------------------------------------------------------------------------
__global__ void __launch_bounds__(256) rmsnorm_kernel(
    float* __restrict__ x, const float* __restrict__ w, int ld, int n)
{
    const int row = blockIdx.x;
    float* xr = x + (size_t)row * ld;

    float s = 0.f;
    for (int i = threadIdx.x; i < n; i += 256) {
        float v = xr[i];
        s += v * v;
    }
    __shared__ float red[8];
    #pragma unroll
    for (int o = 16; o; o >>= 1) s += __shfl_xor_sync(0xffffffffu, s, o);
    if ((threadIdx.x & 31) == 0) red[threadIdx.x >> 5] = s;
    __syncthreads();
    if (threadIdx.x < 32) {
        float v = (threadIdx.x < 8) ? red[threadIdx.x] : 0.f;
        #pragma unroll
        for (int o = 4; o; o >>= 1) v += __shfl_xor_sync(0xffffffffu, v, o);
        if (threadIdx.x == 0) red[0] = v;
    }
    __syncthreads();
    const float r = rsqrtf(red[0] / (float)n + EPS);
    for (int i = threadIdx.x; i < n; i += 256)
        xr[i] = w[i] * xr[i] * r;
}

// ---------------------------------------------------------------------------
// RoPE + assemble per-head contiguous Q/K/V. (pos_ids dtype sniffing: word 1
// is 0 for int64 little-endian, nonzero (=1) for int32 arange.)
// ---------------------------------------------------------------------------
__global__ void __launch_bounds__(256) assemble_kernel(
    const void* __restrict__ pos_ids)
{
    const int t = blockIdx.x;
    const int tid = threadIdx.x;

    __shared__ float cs[DR], sn[DR], kr[DR], kx[DR];
    __shared__ float s_pos;

    if (tid == 0) {
        const int* p32 = (const int*)pos_ids;
        long long pv;
        if (p32[1] == 0) pv = ((const long long*)pos_ids)[t];
        else             pv = (long long)p32[t];
        s_pos = (float)pv;
    }
    __syncthreads();

    const float pos = s_pos;
    if (tid < DR) {
        const int j = tid & 31;
        double e = -((double)(2 * j) / (double)DR) * 13.287712379549449;
        float inv = (float)exp2(e);
        float ang = pos * inv;
        cs[tid] = cosf(ang);
        sn[tid] = sinf(ang);
        kx[tid] = g_kva[(size_t)t * (KVR + DR) + KVR + tid];
    }
    __syncthreads();
    if (tid < DR) {
        float v;
        if (tid < 32) v = kx[tid] * cs[tid] - kx[tid + 32] * sn[tid];
        else          v = kx[tid] * cs[tid] + kx[tid - 32] * sn[tid];
        kr[tid] = v;
    }
    __syncthreads();

    const float scale = rsqrtf((float)DQK);

    for (int h = 0; h < NH; h++) {
        const float* qrow  = g_q   + (size_t)t * NH * DQK + h * DQK;
        const float* kvrow = g_kvb + (size_t)t * NH * (DN + DV) + h * (DN + DV);
        float* Qd = g_Qf + ((size_t)h * S_LEN + t) * DQK;
        float* Kd = g_Kf + ((size_t)h * S_LEN + t) * DQK;
        float* Vd = g_Vf + ((size_t)h * S_LEN + t) * DV;

        for (int d = tid; d < DQK; d += 256) {
            float v;
            if (d < DN) v = qrow[d];
            else {
                int i = d - DN;
                float x = qrow[d];
                if (i < 32) v = x * cs[i] - qrow[DN + i + 32] * sn[i];
                else        v = x * cs[i] + qrow[DN + i - 32] * sn[i];
            }
            Qd[d] = v * scale;
        }
        for (int d = tid; d < DQK; d += 256)
            Kd[d] = (d < DN) ? kvrow[d] : kr[d - DN];
        for (int d = tid; d < DV; d += 256)
            Vd[d] = kvrow[DN + d];
    }
}

// ---------------------------------------------------------------------------
// Flash attention (causal), fp32. One block per (64-query tile, head).
// ---------------------------------------------------------------------------
constexpr int BQ = 64, BK = 64;
constexpr int QS_STRIDE = 193;
constexpr int KS_STRIDE = 193;
constexpr int VS_STRIDE = 129;
constexpr int SS_STRIDE = 65;
constexpr int FLASH_SMEM_FLOATS =
    BQ * QS_STRIDE + BK * KS_STRIDE + BK * VS_STRIDE + BQ * SS_STRIDE + 3 * BQ;
constexpr size_t FLASH_SMEM_BYTES = FLASH_SMEM_FLOATS * sizeof(float);

__global__ void __launch_bounds__(256) flash_kernel()
{
    const int h  = blockIdx.y;
    const int qt = blockIdx.x;
    const int q0 = qt * BQ;
    const int tid = threadIdx.x;
    const int tx = tid & 15;
    const int ty = tid >> 4;

    extern __shared__ float smf[];
    float* Qs   = smf;
    float* Ks   = Qs + BQ * QS_STRIDE;
    float* Vs   = Ks + BK * KS_STRIDE;
    float* Ss   = Vs + BK * VS_STRIDE;
    float* mrow = Ss + BQ * SS_STRIDE;
    float* lrow = mrow + BQ;
    float* arow = lrow + BQ;

    const float* Qg = g_Qf + ((size_t)h * S_LEN + q0) * DQK;
    const float* Kg = g_Kf + (size_t)h * S_LEN * DQK;
    const float* Vg = g_Vf + (size_t)h * S_LEN * DV;

    for (int idx = tid; idx < BQ * (DQK / 4); idx += 256) {
        int r  = idx / (DQK / 4);
        int c4 = (idx % (DQK / 4)) * 4;
        float4 v = *(const float4*)(Qg + (size_t)r * DQK + c4);
        float* dst = Qs + r * QS_STRIDE + c4;
        dst[0] = v.x; dst[1] = v.y; dst[2] = v.z; dst[3] = v.w;
    }
    if (tid < BQ) { mrow[tid] = -1e30f; lrow[tid] = 0.f; }

    float o[4][8];
    #pragma unroll
    for (int i = 0; i < 4; i++)
        #pragma unroll
        for (int c = 0; c < 8; c++) o[i][c] = 0.f;

    __syncthreads();

    const int nkt = qt + 1;
    for (int kt = 0; kt < nkt; kt++) {
        const int k0 = kt * BK;

        for (int idx = tid; idx < BK * (DQK / 4); idx += 256) {
            int r  = idx / (DQK / 4);
            int c4 = (idx % (DQK / 4)) * 4;
            float4 v = *(const float4*)(Kg + (size_t)(k0 + r) * DQK + c4);
            float* dst = Ks + r * KS_STRIDE + c4;
            dst[0] = v.x; dst[1] = v.y; dst[2] = v.z; dst[3] = v.w;
        }
        for (int idx = tid; idx < BK * (DV / 4); idx += 256) {
            int r  = idx / (DV / 4);
            int c4 = (idx % (DV / 4)) * 4;
            float4 v = *(const float4*)(Vg + (size_t)(k0 + r) * DV + c4);
            float* dst = Vs + r * VS_STRIDE + c4;
            dst[0] = v.x; dst[1] = v.y; dst[2] = v.z; dst[3] = v.w;
        }
        __syncthreads();

        float s[4][4];
        #pragma unroll
        for (int i = 0; i < 4; i++)
            #pragma unroll
            for (int j = 0; j < 4; j++) s[i][j] = 0.f;

        #pragma unroll 4
        for (int d = 0; d < DQK; d++) {
            float a[4], b[4];
            #pragma unroll
            for (int i = 0; i < 4; i++) a[i] = Qs[(ty + 16 * i) * QS_STRIDE + d];
            #pragma unroll
            for (int j = 0; j < 4; j++) b[j] = Ks[(tx + 16 * j) * KS_STRIDE + d];
            #pragma unroll
            for (int i = 0; i < 4; i++)
                #pragma unroll
                for (int j = 0; j < 4; j++)
                    s[i][j] = fmaf(a[i], b[j], s[i][j]);
        }

        const bool diag = (kt == qt);
        #pragma unroll
        for (int i = 0; i < 4; i++) {
            int qr = ty + 16 * i;
            #pragma unroll
            for (int j = 0; j < 4; j++) {
                int kc = tx + 16 * j;
                float v = s[i][j];
                if (diag && kc > qr) v = -1e30f;
                Ss[qr * SS_STRIDE + kc] = v;
            }
        }
        __syncthreads();

        if (tid < BQ) {
            const int r = tid;
            float* srow = Ss + r * SS_STRIDE;
            float mold = mrow[r];
            float mx = mold;
            #pragma unroll 8
            for (int j = 0; j < BK; j++) mx = fmaxf(mx, srow[j]);
            float alpha = __expf(mold - mx);
            float sum = 0.f;
            #pragma unroll 8
            for (int j = 0; j < BK; j++) {
                float p = __expf(srow[j] - mx);
                srow[j] = p;
                sum += p;
            }
            mrow[r] = mx;
            lrow[r] = lrow[r] * alpha + sum;
            arow[r] = alpha;
        }
        __syncthreads();

        float al[4];
        #pragma unroll
        for (int i = 0; i < 4; i++) al[i] = arow[ty + 16 * i];
        #pragma unroll
        for (int i = 0; i < 4; i++)
            #pragma unroll
            for (int c = 0; c < 8; c++) o[i][c] *= al[i];

        #pragma unroll 4
        for (int j = 0; j < BK; j++) {
            float p[4], v[8];
            #pragma unroll
            for (int i = 0; i < 4; i++) p[i] = Ss[(ty + 16 * i) * SS_STRIDE + j];
            #pragma unroll
            for (int c = 0; c < 8; c++) v[c] = Vs[j * VS_STRIDE + tx + 16 * c];
            #pragma unroll
            for (int i = 0; i < 4; i++)
                #pragma unroll
                for (int c = 0; c < 8; c++)
                    o[i][c] = fmaf(p[i], v[c], o[i][c]);
        }
        __syncthreads();
    }

    #pragma unroll
    for (int i = 0; i < 4; i++) {
        const int qr = ty + 16 * i;
        const float inv = __fdividef(1.f, lrow[qr]);
        #pragma unroll
        for (int c = 0; c < 8; c++)
            g_attn[(size_t)(q0 + qr) * (NH * DV) + h * DV + tx + 16 * c] =
                o[i][c] * inv;
    }
}

// ---------------------------------------------------------------------------
// Launch
// ---------------------------------------------------------------------------
extern "C" void kernel_launch(void* const* d_in, const int* in_sizes, int n_in,
                              void* d_out, int out_size)
{
    const float* hs       = (const float*)d_in[0];
    const void*  pos_ids  = d_in[1];
    const float* q_a_w    = (const float*)d_in[2];
    const float* q_a_ln_w = (const float*)d_in[3];
    const float* q_b_w    = (const float*)d_in[4];
    const float* kv_a_w   = (const float*)d_in[5];
    const float* kv_a_ln_w= (const float*)d_in[6];
    const float* kv_b_w   = (const float*)d_in[7];
    const float* o_w      = (const float*)d_in[8];
    float*       out      = (float*)d_out;

    float *p_qa, *p_q, *p_kva, *p_kvb, *p_attn;
    cudaGetSymbolAddress((void**)&p_qa,   g_qa);
    cudaGetSymbolAddress((void**)&p_q,    g_q);
    cudaGetSymbolAddress((void**)&p_kva,  g_kva);
    cudaGetSymbolAddress((void**)&p_kvb,  g_kvb);
    cudaGetSymbolAddress((void**)&p_attn, g_attn);

    cudaFuncSetAttribute(flash_kernel,
                         cudaFuncAttributeMaxDynamicSharedMemorySize,
                         (int)FLASH_SMEM_BYTES);
    cudaFuncSetAttribute(gemm_tf32_kernel,
                         cudaFuncAttributeMaxDynamicSharedMemorySize,
                         GEMM_SMEM_BYTES);

    // 1. q_a = hs @ q_a_w^T   (M=2048, N=1536, K=2048)
    gemm_tf32_kernel<<<dim3(QR / 128, S_LEN / 128), 256, GEMM_SMEM_BYTES>>>(
        hs, HID, q_a_w, p_qa, QR, HID);

    // 2. rmsnorm(q_a)
    rmsnorm_kernel<<<S_LEN, 256>>>(p_qa, q_a_ln_w, QR, QR);

    // 3. q = q_a_n @ q_b_w^T  (N=3072, K=1536)
    gemm_tf32_kernel<<<dim3(NH * DQK / 128, S_LEN / 128), 256, GEMM_SMEM_BYTES>>>(
        p_qa, QR, q_b_w, p_q, NH * DQK, QR);

    // 4. kv_a = hs @ kv_a_w^T (N=576, K=2048)
    gemm_tf32_kernel<<<dim3((KVR + DR + 127) / 128, S_LEN / 128), 256, GEMM_SMEM_BYTES>>>(
        hs, HID, kv_a_w, p_kva, KVR + DR, HID);

    // 5. rmsnorm(kv_a[:, :512])
    rmsnorm_kernel<<<S_LEN, 256>>>(p_kva, kv_a_ln_w, KVR + DR, KVR);

    // 6. kv_b = ckv @ kv_b_w^T (N=4096, K=512, lda=576)
    gemm_tf32_kernel<<<dim3(NH * (DN + DV) / 128, S_LEN / 128), 256, GEMM_SMEM_BYTES>>>(
        p_kva, KVR + DR, kv_b_w, p_kvb, NH * (DN + DV), KVR);

    // 7. RoPE + assemble
    assemble_kernel<<<S_LEN, 256>>>(pos_ids);

    // 8. causal flash attention
    flash_kernel<<<dim3(S_LEN / BQ, NH), 256, FLASH_SMEM_BYTES>>>();

    // 9. out = attn @ o_w^T (N=2048, K=2048)
    gemm_tf32_kernel<<<dim3(HID / 128, S_LEN / 128), 256, GEMM_SMEM_BYTES>>>(
        p_attn, NH * DV, o_w, out, HID, HID);
}

// round 4
// speedup vs baseline: 1.1755x; 1.0036x over previous
#include <cuda_runtime.h>
#include <cstdint>

// ---------------------------------------------------------------------------
// Problem constants
// ---------------------------------------------------------------------------
constexpr int S_LEN  = 2048;
constexpr int HID    = 2048;
constexpr int NH     = 16;
constexpr int QR     = 1536;
constexpr int KVR    = 512;
constexpr int DN     = 128;   // d_nope
constexpr int DR     = 64;    // d_rope
constexpr int DQK    = 192;   // d_nope + d_rope
constexpr int DV     = 128;
constexpr float EPS  = 1e-6f;

// ---------------------------------------------------------------------------
// Scratch (device globals; no allocation allowed)
// ---------------------------------------------------------------------------
__device__ float g_qa  [S_LEN * QR];
__device__ float g_q   [S_LEN * NH * DQK];
__device__ float g_kva [S_LEN * (KVR + DR)];
__device__ float g_kvb [S_LEN * NH * (DN + DV)];
__device__ float g_Qf  [NH * S_LEN * DQK];
__device__ float g_Kf  [NH * S_LEN * DQK];
__device__ float g_Vf  [NH * S_LEN * DV];
__device__ float g_attn[S_LEN * NH * DV];

// ---------------------------------------------------------------------------
// TF32 helpers
// ---------------------------------------------------------------------------
__device__ __forceinline__ uint32_t f2tf32(float x) {
    uint32_t r;
    asm("cvt.rna.tf32.f32 %0, %1;" : "=r"(r) : "f"(x));
    return r;
}

__device__ __forceinline__ void mma_tf32(float* c, const uint4& a, const uint2& b) {
    asm volatile(
        "mma.sync.aligned.m16n8k8.row.col.f32.tf32.tf32.f32 "
        "{%0,%1,%2,%3}, {%4,%5,%6,%7}, {%8,%9}, {%0,%1,%2,%3};"
        : "+f"(c[0]), "+f"(c[1]), "+f"(c[2]), "+f"(c[3])
        : "r"(a.x), "r"(a.y), "r"(a.z), "r"(a.w), "r"(b.x), "r"(b.y));
}

// ---------------------------------------------------------------------------
// 3xTF32 NT GEMM: C[M,N] = A[M,K(lda)] * B[N,K]^T, fp32 in/out.
// CTA tile 128x128, BK=16, 256 threads (8 warps, warp tile 64x32),
// double-buffered smem with fragment-permuted layout, hi/lo TF32 planes.
// Requires: M % 128 == 0, K % 16 == 0. N arbitrary (guards; N % 8 == 0).
//
// Smem (dynamic, 64KB):
//   sA: [stage(2)][plane(2)][2048 floats]   (128 rows x 16 k, permuted)
//   sB: [stage(2)][plane(2)][2048 floats]   (128 n   x 16 k, permuted)
// A slot (m16k8 frag of m-tile mt, k8-tile kt):
//   off = (mt*2+kt)*128 + lane*4 + reg  (reg = (khalf)*2 + (rowhalf))
// B slot (n8k8 frag): off = (nt*2+kt)*64 + lane*2 + reg (reg = khalf)
// ---------------------------------------------------------------------------
constexpr int GEMM_SMEM_BYTES = 2 * 2 * 2048 * 4 * 2;   // 65536

__device__ __forceinline__ void stage_chunk(
    float* __restrict__ sAh, float* __restrict__ sAl,
    float* __restrict__ sBh, float* __restrict__ sBl,
    const float4& a0, const float4& a1,
    const float4& b0, const float4& b1,
    int abase, int s_mbit, int bbase)
{
    float av[8] = {a0.x, a0.y, a0.z, a0.w, a1.x, a1.y, a1.z, a1.w};
    float bv[8] = {b0.x, b0.y, b0.z, b0.w, b1.x, b1.y, b1.z, b1.w};
    #pragma unroll
    for (int e = 0; e < 8; e++) {
        uint32_t ahi = f2tf32(av[e]);
        uint32_t alo = f2tf32(av[e] - __uint_as_float(ahi));
        int aoff = abase + (e & 3) * 4 + (e >> 2) * 2 + s_mbit;
        sAh[aoff] = __uint_as_float(ahi);
        sAl[aoff] = __uint_as_float(alo);

        uint32_t bhi = f2tf32(bv[e]);
        uint32_t blo = f2tf32(bv[e] - __uint_as_float(bhi));
        int boff = bbase + (e & 3) * 2 + (e >> 2);
        sBh[boff] = __uint_as_float(bhi);
        sBl[boff] = __uint_as_float(blo);
    }
}

__global__ void __launch_bounds__(256) gemm_tf32_kernel(
    const float* __restrict__ A, int lda,
    const float* __restrict__ B,
    float* __restrict__ C,
    int N, int K)
{
    extern __shared__ float smg[];
    float* sA = smg;            // 8192 floats
    float* sB = smg + 8192;     // 8192 floats

    const int tid  = threadIdx.x;
    const int lane = tid & 31;
    const int warp = tid >> 5;
    const int wm = warp >> 2;   // 0..1
    const int wn = warp & 3;    // 0..3
    const int m0 = blockIdx.y * 128;
    const int n0 = blockIdx.x * 128;

    // staging coordinates: thread pair (2u, 2u+1) covers row u, k-halves 0/1
    const int srow  = tid >> 1;        // 0..127
    const int kt_st = tid & 1;         // k8 subtile within BK=16
    const int s_mbit = (srow >> 3) & 1;
    const int abase = ((srow >> 4) * 2 + kt_st) * 128 + (srow & 7) * 16;
    const int bbase = ((srow >> 3) * 2 + kt_st) * 64  + (srow & 7) * 8;
    const bool bvalid = (n0 + srow) < N;

    const float* Ag = A + (size_t)(m0 + srow) * lda + kt_st * 8;
    const float* Bg = B + (size_t)(n0 + srow) * K   + kt_st * 8;

    float acc[4][4][4];
    #pragma unroll
    for (int i = 0; i < 4; i++)
        #pragma unroll
        for (int j = 0; j < 4; j++)
            #pragma unroll
            for (int r = 0; r < 4; r++) acc[i][j][r] = 0.f;

    const int nc = K / 16;
    const float4 z4 = make_float4(0.f, 0.f, 0.f, 0.f);

    // prologue: stage chunk 0 into stage 0
    {
        float4 a0 = *(const float4*)(Ag);
        float4 a1 = *(const float4*)(Ag + 4);
        float4 b0 = bvalid ? *(const float4*)(Bg)     : z4;
        float4 b1 = bvalid ? *(const float4*)(Bg + 4) : z4;
        stage_chunk(sA, sA + 2048, sB, sB + 2048, a0, a1, b0, b1,
                    abase, s_mbit, bbase);
    }
    __syncthreads();

    for (int c = 0; c < nc; c++) {
        const int s = c & 1;

        // prefetch next chunk gmem -> regs
        float4 pa0 = z4, pa1 = z4, pb0 = z4, pb1 = z4;
        if (c + 1 < nc) {
            const float* ap = Ag + (c + 1) * 16;
            pa0 = *(const float4*)(ap);
            pa1 = *(const float4*)(ap + 4);
            if (bvalid) {
                const float* bp = Bg + (c + 1) * 16;
                pb0 = *(const float4*)(bp);
                pb1 = *(const float4*)(bp + 4);
            }
        }

        // compute on stage s
        const float* pAh = sA + (s * 2 + 0) * 2048;
        const float* pAl = sA + (s * 2 + 1) * 2048;
        const float* pBh = sB + (s * 2 + 0) * 2048;
        const float* pBl = sB + (s * 2 + 1) * 2048;

        #pragma unroll
        for (int kt = 0; kt < 2; kt++) {
            uint4 Ah[4], Al[4];
            uint2 Bh[4], Bl[4];
            #pragma unroll
            for (int i = 0; i < 4; i++) {
                int off = (((wm * 4 + i) * 2 + kt) * 128) + lane * 4;
                Ah[i] = *(const uint4*)&pAh[off];
                Al[i] = *(const uint4*)&pAl[off];
            }
            #pragma unroll
            for (int j = 0; j < 4; j++) {
                int off = (((wn * 4 + j) * 2 + kt) * 64) + lane * 2;
                Bh[j] = *(const uint2*)&pBh[off];
                Bl[j] = *(const uint2*)&pBl[off];
            }
            #pragma unroll
            for (int i = 0; i < 4; i++)
                #pragma unroll
                for (int j = 0; j < 4; j++) {
                    mma_tf32(acc[i][j], Ah[i], Bh[j]);
                    mma_tf32(acc[i][j], Ah[i], Bl[j]);
                    mma_tf32(acc[i][j], Al[i], Bh[j]);
                }
        }

        // store prefetched chunk into the other stage
        if (c + 1 < nc) {
            const int t = s ^ 1;
            stage_chunk(sA + (t * 2) * 2048, sA + (t * 2 + 1) * 2048,
                        sB + (t * 2) * 2048, sB + (t * 2 + 1) * 2048,
                        pa0, pa1, pb0, pb1, abase, s_mbit, bbase);
        }
        __syncthreads();
    }

    // epilogue
    const int g = lane >> 2;
    const int q = lane & 3;
    #pragma unroll
    for (int i = 0; i < 4; i++) {
        const int row = m0 + wm * 64 + i * 16 + g;
        #pragma unroll
        for (int j = 0; j < 4; j++) {
            const int colb = n0 + wn * 32 + j * 8;
            if (colb < N) {
                const int col = colb + 2 * q;
                *(float2*)&C[(size_t)row * N + col] =
                    make_float2(acc[i][j][0], acc[i][j][1]);
                *(float2*)&C[(size_t)(row + 8) * N + col] =
                    make_float2(acc[i][j][2], acc[i][j][3]);
            }
        }
    }
}

// ---------------------------------------------------------------------------
// RMSNorm (in place)
// ---------------------------------------------------------------------------
__global__ void __launch_bounds__(256) rmsnorm_kernel(
    float* __restrict__ x, const float* __restrict__ w, int ld, int n)
{
    const int row = blockIdx.x;
    float* xr = x + (size_t)row * ld;

    float s = 0.f;
    for (int i = threadIdx.x; i < n; i += 256) {
        float v = xr[i];
        s += v * v;
    }
    __shared__ float red[8];
    #pragma unroll
    for (int o = 16; o; o >>= 1) s += __shfl_xor_sync(0xffffffffu, s, o);
    if ((threadIdx.x & 31) == 0) red[threadIdx.x >> 5] = s;
    __syncthreads();
    if (threadIdx.x < 32) {
        float v = (threadIdx.x < 8) ? red[threadIdx.x] : 0.f;
        #pragma unroll
        for (int o = 4; o; o >>= 1) v += __shfl_xor_sync(0xffffffffu, v, o);
        if (threadIdx.x == 0) red[0] = v;
    }
    __syncthreads();
    const float r = rsqrtf(red[0] / (float)n + EPS);
    for (int i = threadIdx.x; i < n; i += 256)
        xr[i] = w[i] * xr[i] * r;
}

// ---------------------------------------------------------------------------
// RoPE + assemble per-head contiguous Q/K/V. (pos_ids dtype sniffing: word 1
// is 0 for int64 little-endian, nonzero (=1) for int32 arange.)
// ---------------------------------------------------------------------------
__global__ void __launch_bounds__(256) assemble_kernel(
    const void* __restrict__ pos_ids)
{
    const int t = blockIdx.x;
    const int tid = threadIdx.x;

    __shared__ float cs[DR], sn[DR], kr[DR], kx[DR];
    __shared__ float s_pos;

    if (tid == 0) {
        const int* p32 = (const int*)pos_ids;
        long long pv;
        if (p32[1] == 0) pv = ((const long long*)pos_ids)[t];
        else             pv = (long long)p32[t];
        s_pos = (float)pv;
    }
    __syncthreads();

    const float pos = s_pos;
    if (tid < DR) {
        const int j = tid & 31;
        double e = -((double)(2 * j) / (double)DR) * 13.287712379549449;
        float inv = (float)exp2(e);
        float ang = pos * inv;
        cs[tid] = cosf(ang);
        sn[tid] = sinf(ang);
        kx[tid] = g_kva[(size_t)t * (KVR + DR) + KVR + tid];
    }
    __syncthreads();
    if (tid < DR) {
        float v;
        if (tid < 32) v = kx[tid] * cs[tid] - kx[tid + 32] * sn[tid];
        else          v = kx[tid] * cs[tid] + kx[tid - 32] * sn[tid];
        kr[tid] = v;
    }
    __syncthreads();

    const float scale = rsqrtf((float)DQK);

    for (int h = 0; h < NH; h++) {
        const float* qrow  = g_q   + (size_t)t * NH * DQK + h * DQK;
        const float* kvrow = g_kvb + (size_t)t * NH * (DN + DV) + h * (DN + DV);
        float* Qd = g_Qf + ((size_t)h * S_LEN + t) * DQK;
        float* Kd = g_Kf + ((size_t)h * S_LEN + t) * DQK;
        float* Vd = g_Vf + ((size_t)h * S_LEN + t) * DV;

        for (int d = tid; d < DQK; d += 256) {
            float v;
            if (d < DN) v = qrow[d];
            else {
                int i = d - DN;
                float x = qrow[d];
                if (i < 32) v = x * cs[i] - qrow[DN + i + 32] * sn[i];
                else        v = x * cs[i] + qrow[DN + i - 32] * sn[i];
            }
            Qd[d] = v * scale;
        }
        for (int d = tid; d < DQK; d += 256)
            Kd[d] = (d < DN) ? kvrow[d] : kr[d - DN];
        for (int d = tid; d < DV; d += 256)
            Vd[d] = kvrow[DN + d];
    }
}

// ---------------------------------------------------------------------------
// Flash attention (causal), fp32. One block per (64-query tile, head).
// ---------------------------------------------------------------------------
constexpr int BQ = 64, BK = 64;
constexpr int QS_STRIDE = 193;
constexpr int KS_STRIDE = 193;
constexpr int VS_STRIDE = 129;
constexpr int SS_STRIDE = 65;
constexpr int FLASH_SMEM_FLOATS =
    BQ * QS_STRIDE + BK * KS_STRIDE + BK * VS_STRIDE + BQ * SS_STRIDE + 3 * BQ;
constexpr size_t FLASH_SMEM_BYTES = FLASH_SMEM_FLOATS * sizeof(float);

__global__ void __launch_bounds__(256) flash_kernel()
{
    const int h  = blockIdx.y;
    const int qt = blockIdx.x;
    const int q0 = qt * BQ;
    const int tid = threadIdx.x;
    const int tx = tid & 15;
    const int ty = tid >> 4;

    extern __shared__ float smf[];
    float* Qs   = smf;
    float* Ks   = Qs + BQ * QS_STRIDE;
    float* Vs   = Ks + BK * KS_STRIDE;
    float* Ss   = Vs + BK * VS_STRIDE;
    float* mrow = Ss + BQ * SS_STRIDE;
    float* lrow = mrow + BQ;
    float* arow = lrow + BQ;

    const float* Qg = g_Qf + ((size_t)h * S_LEN + q0) * DQK;
    const float* Kg = g_Kf + (size_t)h * S_LEN * DQK;
    const float* Vg = g_Vf + (size_t)h * S_LEN * DV;

    for (int idx = tid; idx < BQ * (DQK / 4); idx += 256) {
        int r  = idx / (DQK / 4);
        int c4 = (idx % (DQK / 4)) * 4;
        float4 v = *(const float4*)(Qg + (size_t)r * DQK + c4);
        float* dst = Qs + r * QS_STRIDE + c4;
        dst[0] = v.x; dst[1] = v.y; dst[2] = v.z; dst[3] = v.w;
    }
    if (tid < BQ) { mrow[tid] = -1e30f; lrow[tid] = 0.f; }

    float o[4][8];
    #pragma unroll
    for (int i = 0; i < 4; i++)
        #pragma unroll
        for (int c = 0; c < 8; c++) o[i][c] = 0.f;

    __syncthreads();

    const int nkt = qt + 1;
    for (int kt = 0; kt < nkt; kt++) {
        const int k0 = kt * BK;

        for (int idx = tid; idx < BK * (DQK / 4); idx += 256) {
            int r  = idx / (DQK / 4);
            int c4 = (idx % (DQK / 4)) * 4;
            float4 v = *(const float4*)(Kg + (size_t)(k0 + r) * DQK + c4);
            float* dst = Ks + r * KS_STRIDE + c4;
            dst[0] = v.x; dst[1] = v.y; dst[2] = v.z; dst[3] = v.w;
        }
        for (int idx = tid; idx < BK * (DV / 4); idx += 256) {
            int r  = idx / (DV / 4);
            int c4 = (idx % (DV / 4)) * 4;
            float4 v = *(const float4*)(Vg + (size_t)(k0 + r) * DV + c4);
            float* dst = Vs + r * VS_STRIDE + c4;
            dst[0] = v.x; dst[1] = v.y; dst[2] = v.z; dst[3] = v.w;
        }
        __syncthreads();

        float s[4][4];
        #pragma unroll
        for (int i = 0; i < 4; i++)
            #pragma unroll
            for (int j = 0; j < 4; j++) s[i][j] = 0.f;

        #pragma unroll 4
        for (int d = 0; d < DQK; d++) {
            float a[4], b[4];
            #pragma unroll
            for (int i = 0; i < 4; i++) a[i] = Qs[(ty + 16 * i) * QS_STRIDE + d];
            #pragma unroll
            for (int j = 0; j < 4; j++) b[j] = Ks[(tx + 16 * j) * KS_STRIDE + d];
            #pragma unroll
            for (int i = 0; i < 4; i++)
                #pragma unroll
                for (int j = 0; j < 4; j++)
                    s[i][j] = fmaf(a[i], b[j], s[i][j]);
        }

        const bool diag = (kt == qt);
        #pragma unroll
        for (int i = 0; i < 4; i++) {
            int qr = ty + 16 * i;
            #pragma unroll
            for (int j = 0; j < 4; j++) {
                int kc = tx + 16 * j;
                float v = s[i][j];
                if (diag && kc > qr) v = -1e30f;
                Ss[qr * SS_STRIDE + kc] = v;
            }
        }
        __syncthreads();

        if (tid < BQ) {
            const int r = tid;
            float* srow = Ss + r * SS_STRIDE;
            float mold = mrow[r];
            float mx = mold;
            #pragma unroll 8
            for (int j = 0; j < BK; j++) mx = fmaxf(mx, srow[j]);
            float alpha = __expf(mold - mx);
            float sum = 0.f;
            #pragma unroll 8
            for (int j = 0; j < BK; j++) {
                float p = __expf(srow[j] - mx);
                srow[j] = p;
                sum += p;
            }
            mrow[r] = mx;
            lrow[r] = lrow[r] * alpha + sum;
            arow[r] = alpha;
        }
        __syncthreads();

        float al[4];
        #pragma unroll
        for (int i = 0; i < 4; i++) al[i] = arow[ty + 16 * i];
        #pragma unroll
        for (int i = 0; i < 4; i++)
            #pragma unroll
            for (int c = 0; c < 8; c++) o[i][c] *= al[i];

        #pragma unroll 4
        for (int j = 0; j < BK; j++) {
            float p[4], v[8];
            #pragma unroll
            for (int i = 0; i < 4; i++) p[i] = Ss[(ty + 16 * i) * SS_STRIDE + j];
            #pragma unroll
            for (int c = 0; c < 8; c++) v[c] = Vs[j * VS_STRIDE + tx + 16 * c];
            #pragma unroll
            for (int i = 0; i < 4; i++)
                #pragma unroll
                for (int c = 0; c < 8; c++)
                    o[i][c] = fmaf(p[i], v[c], o[i][c]);
        }
        __syncthreads();
    }

    #pragma unroll
    for (int i = 0; i < 4; i++) {
        const int qr = ty + 16 * i;
        const float inv = __fdividef(1.f, lrow[qr]);
        #pragma unroll
        for (int c = 0; c < 8; c++)
            g_attn[(size_t)(q0 + qr) * (NH * DV) + h * DV + tx + 16 * c] =
                o[i][c] * inv;
    }
}

// ---------------------------------------------------------------------------
// Launch
// ---------------------------------------------------------------------------
extern "C" void kernel_launch(void* const* d_in, const int* in_sizes, int n_in,
                              void* d_out, int out_size)
{
    const float* hs       = (const float*)d_in[0];
    const void*  pos_ids  = d_in[1];
    const float* q_a_w    = (const float*)d_in[2];
    const float* q_a_ln_w = (const float*)d_in[3];
    const float* q_b_w    = (const float*)d_in[4];
    const float* kv_a_w   = (const float*)d_in[5];
    const float* kv_a_ln_w= (const float*)d_in[6];
    const float* kv_b_w   = (const float*)d_in[7];
    const float* o_w      = (const float*)d_in[8];
    float*       out      = (float*)d_out;

    float *p_qa, *p_q, *p_kva, *p_kvb, *p_attn;
    cudaGetSymbolAddress((void**)&p_qa,   g_qa);
    cudaGetSymbolAddress((void**)&p_q,    g_q);
    cudaGetSymbolAddress((void**)&p_kva,  g_kva);
    cudaGetSymbolAddress((void**)&p_kvb,  g_kvb);
    cudaGetSymbolAddress((void**)&p_attn, g_attn);

    cudaFuncSetAttribute(flash_kernel,
                         cudaFuncAttributeMaxDynamicSharedMemorySize,
                         (int)FLASH_SMEM_BYTES);
    cudaFuncSetAttribute(gemm_tf32_kernel,
                         cudaFuncAttributeMaxDynamicSharedMemorySize,
                         GEMM_SMEM_BYTES);

    // 1. q_a = hs @ q_a_w^T   (M=2048, N=1536, K=2048)
    gemm_tf32_kernel<<<dim3(QR / 128, S_LEN / 128), 256, GEMM_SMEM_BYTES>>>(
        hs, HID, q_a_w, p_qa, QR, HID);

    // 2. rmsnorm(q_a)
    rmsnorm_kernel<<<S_LEN, 256>>>(p_qa, q_a_ln_w, QR, QR);

    // 3. q = q_a_n @ q_b_w^T  (N=3072, K=1536)
    gemm_tf32_kernel<<<dim3(NH * DQK / 128, S_LEN / 128), 256, GEMM_SMEM_BYTES>>>(
        p_qa, QR, q_b_w, p_q, NH * DQK, QR);

    // 4. kv_a = hs @ kv_a_w^T (N=576, K=2048)
    gemm_tf32_kernel<<<dim3((KVR + DR + 127) / 128, S_LEN / 128), 256, GEMM_SMEM_BYTES>>>(
        hs, HID, kv_a_w, p_kva, KVR + DR, HID);

    // 5. rmsnorm(kv_a[:, :512])
    rmsnorm_kernel<<<S_LEN, 256>>>(p_kva, kv_a_ln_w, KVR + DR, KVR);

    // 6. kv_b = ckv @ kv_b_w^T (N=4096, K=512, lda=576)
    gemm_tf32_kernel<<<dim3(NH * (DN + DV) / 128, S_LEN / 128), 256, GEMM_SMEM_BYTES>>>(
        p_kva, KVR + DR, kv_b_w, p_kvb, NH * (DN + DV), KVR);

    // 7. RoPE + assemble
    assemble_kernel<<<S_LEN, 256>>>(pos_ids);

    // 8. causal flash attention
    flash_kernel<<<dim3(S_LEN / BQ, NH), 256, FLASH_SMEM_BYTES>>>();

    // 9. out = attn @ o_w^T (N=2048, K=2048)
    gemm_tf32_kernel<<<dim3(HID / 128, S_LEN / 128), 256, GEMM_SMEM_BYTES>>>(
        p_attn, NH * DV, o_w, out, HID, HID);
}

// round 5
// speedup vs baseline: 2.7612x; 2.3489x over previous
#include <cuda_runtime.h>
#include <cuda_fp16.h>
#include <cstdint>

constexpr int S_LEN = 2048, HID = 2048, NH = 16, QR = 1536, KVR = 512;
constexpr int DN = 128, DR = 64, DQK = 192, DV = 128;
constexpr float EPS = 1e-6f;

__device__ float g_qa  [S_LEN * QR];
__device__ float g_q   [S_LEN * NH * DQK];
__device__ float g_kva [S_LEN * (KVR + DR)];
__device__ float g_kvb [S_LEN * NH * (DN + DV)];
__device__ float g_attn[S_LEN * NH * DV];

// fp16 hi/lo fragment-layout arrays for flash attention
__device__ unsigned g_Qh[NH * (S_LEN/16) * 12 * 128];
__device__ unsigned g_Ql[NH * (S_LEN/16) * 12 * 128];
__device__ unsigned g_Kh[NH * (S_LEN/8)  * 12 * 64];
__device__ unsigned g_Kl[NH * (S_LEN/8)  * 12 * 64];
__device__ unsigned g_Vh[NH * (S_LEN/16) * 16 * 64];
__device__ unsigned g_Vl[NH * (S_LEN/16) * 16 * 64];

__device__ __forceinline__ void split2(float x0, float x1,
                                       unsigned& hi, unsigned& lo) {
    __half h0 = __float2half_rn(x0), h1 = __float2half_rn(x1);
    __half l0 = __float2half_rn(x0 - __half2float(h0));
    __half l1 = __float2half_rn(x1 - __half2float(h1));
    hi = (unsigned)__half_as_ushort(h0) | ((unsigned)__half_as_ushort(h1) << 16);
    lo = (unsigned)__half_as_ushort(l0) | ((unsigned)__half_as_ushort(l1) << 16);
}

__device__ __forceinline__ void mma16(float* c, const uint4& a, const uint2& b) {
    asm volatile(
        "mma.sync.aligned.m16n8k16.row.col.f32.f16.f16.f32 "
        "{%0,%1,%2,%3}, {%4,%5,%6,%7}, {%8,%9}, {%0,%1,%2,%3};"
        : "+f"(c[0]), "+f"(c[1]), "+f"(c[2]), "+f"(c[3])
        : "r"(a.x), "r"(a.y), "r"(a.z), "r"(a.w), "r"(b.x), "r"(b.y));
}

// ---------------------------------------------------------------------------
// fp16x3 NT GEMM: C = A[M,K(lda)] * B[N,K]^T, 128x128 CTA, BK=16, 2 CTAs/SM
// ---------------------------------------------------------------------------
__global__ void __launch_bounds__(256, 2) gemm_fp16x3_kernel(
    const float* __restrict__ A, int lda, const float* __restrict__ B,
    float* __restrict__ C, int N, int K)
{
    __shared__ unsigned sAh[2][1024], sAl[2][1024];
    __shared__ unsigned sBh[2][1024], sBl[2][1024];

    const int tid = threadIdx.x, lane = tid & 31, warp = tid >> 5;
    const int wm = warp >> 2, wn = warp & 3;
    const int m0 = blockIdx.y * 128, n0 = blockIdx.x * 128;

    const int srow = tid >> 1, kt = tid & 1;
    const int abase = (srow >> 4) * 128 + (srow & 7) * 16 + kt * 2 + ((srow >> 3) & 1);
    const int bbase = (srow >> 3) * 64 + (srow & 7) * 8 + kt;
    const bool bvalid = (n0 + srow) < N;

    const float* Ag = A + (size_t)(m0 + srow) * lda + kt * 8;
    const float* Bg = B + (size_t)(n0 + srow) * K   + kt * 8;

    float acc[4][4][4];
    #pragma unroll
    for (int i = 0; i < 4; i++)
        #pragma unroll
        for (int j = 0; j < 4; j++)
            #pragma unroll
            for (int r = 0; r < 4; r++) acc[i][j][r] = 0.f;

    const int nc = K / 16;
    const float4 z4 = make_float4(0.f, 0.f, 0.f, 0.f);

    {
        float4 a0 = *(const float4*)(Ag), a1 = *(const float4*)(Ag + 4);
        float4 b0 = bvalid ? *(const float4*)(Bg) : z4;
        float4 b1 = bvalid ? *(const float4*)(Bg + 4) : z4;
        float av[8] = {a0.x,a0.y,a0.z,a0.w,a1.x,a1.y,a1.z,a1.w};
        float bv[8] = {b0.x,b0.y,b0.z,b0.w,b1.x,b1.y,b1.z,b1.w};
        #pragma unroll
        for (int e = 0; e < 8; e += 2) {
            unsigned hi, lo;
            split2(av[e], av[e+1], hi, lo);
            sAh[0][abase + (e>>1)*4] = hi; sAl[0][abase + (e>>1)*4] = lo;
            split2(bv[e], bv[e+1], hi, lo);
            sBh[0][bbase + (e>>1)*2] = hi; sBl[0][bbase + (e>>1)*2] = lo;
        }
    }
    __syncthreads();

    for (int c = 0; c < nc; c++) {
        const int s = c & 1;

        float4 pa0 = z4, pa1 = z4, pb0 = z4, pb1 = z4;
        if (c + 1 < nc) {
            const float* ap = Ag + (c + 1) * 16;
            pa0 = *(const float4*)(ap); pa1 = *(const float4*)(ap + 4);
            if (bvalid) {
                const float* bp = Bg + (c + 1) * 16;
                pb0 = *(const float4*)(bp); pb1 = *(const float4*)(bp + 4);
            }
        }

        uint4 Ah[4], Al[4];
        #pragma unroll
        for (int i = 0; i < 4; i++) {
            int off = (wm * 4 + i) * 128 + lane * 4;
            Ah[i] = *(const uint4*)&sAh[s][off];
            Al[i] = *(const uint4*)&sAl[s][off];
        }
        #pragma unroll
        for (int j = 0; j < 4; j++) {
            int off = (wn * 4 + j) * 64 + lane * 2;
            uint2 Bh = *(const uint2*)&sBh[s][off];
            uint2 Bl = *(const uint2*)&sBl[s][off];
            #pragma unroll
            for (int i = 0; i < 4; i++) mma16(acc[i][j], Ah[i], Bh);
            #pragma unroll
            for (int i = 0; i < 4; i++) mma16(acc[i][j], Ah[i], Bl);
            #pragma unroll
            for (int i = 0; i < 4; i++) mma16(acc[i][j], Al[i], Bh);
        }

        if (c + 1 < nc) {
            const int t = s ^ 1;
            float av[8] = {pa0.x,pa0.y,pa0.z,pa0.w,pa1.x,pa1.y,pa1.z,pa1.w};
            float bv[8] = {pb0.x,pb0.y,pb0.z,pb0.w,pb1.x,pb1.y,pb1.z,pb1.w};
            #pragma unroll
            for (int e = 0; e < 8; e += 2) {
                unsigned hi, lo;
                split2(av[e], av[e+1], hi, lo);
                sAh[t][abase + (e>>1)*4] = hi; sAl[t][abase + (e>>1)*4] = lo;
                split2(bv[e], bv[e+1], hi, lo);
                sBh[t][bbase + (e>>1)*2] = hi; sBl[t][bbase + (e>>1)*2] = lo;
            }
        }
        __syncthreads();
    }

    const int g = lane >> 2, q = lane & 3;
    #pragma unroll
    for (int i = 0; i < 4; i++) {
        const int row = m0 + wm * 64 + i * 16 + g;
        #pragma unroll
        for (int j = 0; j < 4; j++) {
            const int colb = n0 + wn * 32 + j * 8;
            if (colb < N) {
                const int col = colb + 2 * q;
                *(float2*)&C[(size_t)row * N + col] =
                    make_float2(acc[i][j][0], acc[i][j][1]);
                *(float2*)&C[(size_t)(row + 8) * N + col] =
                    make_float2(acc[i][j][2], acc[i][j][3]);
            }
        }
    }
}

__global__ void __launch_bounds__(256) rmsnorm_kernel(
    float* __restrict__ x, const float* __restrict__ w, int ld, int n)
{
    const int row = blockIdx.x;
    float* xr = x + (size_t)row * ld;
    float s = 0.f;
    for (int i = threadIdx.x; i < n; i += 256) { float v = xr[i]; s += v * v; }
    __shared__ float red[8];
    #pragma unroll
    for (int o = 16; o; o >>= 1) s += __shfl_xor_sync(0xffffffffu, s, o);
    if ((threadIdx.x & 31) == 0) red[threadIdx.x >> 5] = s;
    __syncthreads();
    if (threadIdx.x < 32) {
        float v = (threadIdx.x < 8) ? red[threadIdx.x] : 0.f;
        #pragma unroll
        for (int o = 4; o; o >>= 1) v += __shfl_xor_sync(0xffffffffu, v, o);
        if (threadIdx.x == 0) red[0] = v;
    }
    __syncthreads();
    const float r = rsqrtf(red[0] / (float)n + EPS);
    for (int i = threadIdx.x; i < n; i += 256) xr[i] = w[i] * xr[i] * r;
}

// ---------------------------------------------------------------------------
// Assemble: RoPE + hi/lo split into fragment layouts. Block per token pair.
// ---------------------------------------------------------------------------
__global__ void __launch_bounds__(256) assemble_kernel(
    const void* __restrict__ pos_ids)
{
    const int b = blockIdx.x, t0 = 2 * b, tid = threadIdx.x;
    __shared__ float cs[2][DR], sn[2][DR], kr[2][DR];
    __shared__ float posv[2];

    if (tid < 2) {
        const int* p32 = (const int*)pos_ids;
        int t = t0 + tid;
        long long pv = (p32[1] == 0) ? ((const long long*)pos_ids)[t]
                                     : (long long)p32[t];
        posv[tid] = (float)pv;
    }
    __syncthreads();
    if (tid < 128) {
        int tok = tid >> 6, i = tid & 63, j = i & 31;
        double e = -((double)(2 * j) / 64.0) * 13.287712379549449;
        float ang = posv[tok] * (float)exp2(e);
        cs[tok][i] = cosf(ang); sn[tok][i] = sinf(ang);
    }
    __syncthreads();
    if (tid < 128) {
        int tok = tid >> 6, i = tid & 63;
        const float* kx = g_kva + (size_t)(t0 + tok) * (KVR + DR) + KVR;
        kr[tok][i] = (i < 32) ? kx[i] * cs[tok][i] - kx[i + 32] * sn[tok][i]
                              : kx[i] * cs[tok][i] + kx[i - 32] * sn[tok][i];
    }
    __syncthreads();

    const float scale = rsqrtf((float)DQK);

    for (int h = 0; h < NH; h++) {
        for (int w = tid; w < 192; w += 256) {          // Q
            int tok = w / 96, pp = w % 96, d = 2 * pp;
            int t = t0 + tok;
            const float* qrow = g_q + (size_t)t * (NH * DQK) + h * DQK;
            float v0, v1;
            if (d < DN) { v0 = qrow[d]; v1 = qrow[d + 1]; }
            else {
                int i = d - DN;
                if (i < 32) {
                    v0 = qrow[d]   * cs[tok][i]   - qrow[d + 32] * sn[tok][i];
                    v1 = qrow[d+1] * cs[tok][i+1] - qrow[d + 33] * sn[tok][i+1];
                } else {
                    v0 = qrow[d]   * cs[tok][i]   + qrow[d - 32] * sn[tok][i];
                    v1 = qrow[d+1] * cs[tok][i+1] + qrow[d - 31] * sn[tok][i+1];
                }
            }
            v0 *= scale; v1 *= scale;
            unsigned hi, lo; split2(v0, v1, hi, lo);
            int mt = t >> 4, r = t & 15;
            size_t off = ((size_t)(h * 128 + mt) * 12 + (d >> 4)) * 128
                       + ((r & 7) * 4 + ((d & 7) >> 1)) * 4
                       + (((d >> 3) & 1) * 2 + (r >> 3));
            g_Qh[off] = hi; g_Ql[off] = lo;
        }
        for (int w = tid; w < 192; w += 256) {          // K
            int tok = w / 96, pp = w % 96, d = 2 * pp;
            int t = t0 + tok;
            const float* kvrow = g_kvb + (size_t)t * (NH*(DN+DV)) + h * (DN+DV);
            float v0, v1;
            if (d < DN) { v0 = kvrow[d]; v1 = kvrow[d + 1]; }
            else        { v0 = kr[tok][d - DN]; v1 = kr[tok][d - DN + 1]; }
            unsigned hi, lo; split2(v0, v1, hi, lo);
            int nt = t >> 3, n = t & 7;
            size_t off = ((size_t)(h * 256 + nt) * 12 + (d >> 4)) * 64
                       + (n * 4 + ((d & 7) >> 1)) * 2 + ((d >> 3) & 1);
            g_Kh[off] = hi; g_Kl[off] = lo;
        }
        if (tid < 128) {                                 // V (pairs across tokens)
            int d = tid;
            float v0 = g_kvb[(size_t)t0     * (NH*(DN+DV)) + h*(DN+DV) + DN + d];
            float v1 = g_kvb[(size_t)(t0+1) * (NH*(DN+DV)) + h*(DN+DV) + DN + d];
            unsigned hi, lo; split2(v0, v1, hi, lo);
            size_t off = ((size_t)(h * 128 + (t0 >> 4)) * 16 + (d >> 3)) * 64
                       + ((d & 7) * 4 + ((t0 & 7) >> 1)) * 2 + ((t0 >> 3) & 1);
            g_Vh[off] = hi; g_Vl[off] = lo;
        }
    }
}

// ---------------------------------------------------------------------------
// Flash attention, fp16x3 mma. BQ=128, BK=64, 8 warps.
// ---------------------------------------------------------------------------
constexpr int FLASH_SMEM_U32 = 2*12288 + 2*6144 + 2*4096;
constexpr size_t FLASH_SMEM_BYTES = FLASH_SMEM_U32 * 4;

__global__ void __launch_bounds__(256) flash_kernel()
{
    const int bx = blockIdx.x;
    const int qt = 15 - (bx >> 4);
    const int h  = bx & 15;
    const int q0 = qt * 128;
    const int tid = threadIdx.x, wid = tid >> 5, lane = tid & 31;
    const int g = lane >> 2, q = lane & 3;

    extern __shared__ unsigned smu[];
    unsigned* QH = smu;
    unsigned* QL = QH + 12288;
    unsigned* KH = QL + 12288;
    unsigned* KL = KH + 6144;
    unsigned* VH = KL + 6144;
    unsigned* VL = VH + 4096;

    {
        const uint4* gh = (const uint4*)(g_Qh + (size_t)(h * 128 + qt * 8) * 1536);
        const uint4* gl = (const uint4*)(g_Ql + (size_t)(h * 128 + qt * 8) * 1536);
        uint4* dh = (uint4*)QH; uint4* dl = (uint4*)QL;
        for (int i = tid; i < 3072; i += 256) { dh[i] = gh[i]; dl[i] = gl[i]; }
    }

    float O[16][4];
    #pragma unroll
    for (int nt = 0; nt < 16; nt++)
        #pragma unroll
        for (int r = 0; r < 4; r++) O[nt][r] = 0.f;
    float m0 = -1e30f, m1 = -1e30f, l0 = 0.f, l1 = 0.f;

    const int wrow0 = q0 + wid * 16;
    const int niter = 2 * (qt + 1);

    for (int it = 0; it < niter; it++) {
        const int k0 = it * 64;
        {
            const uint4* gkh = (const uint4*)(g_Kh + (size_t)(h*256 + (k0>>3)) * 768);
            const uint4* gkl = (const uint4*)(g_Kl + (size_t)(h*256 + (k0>>3)) * 768);
            uint4* dkh = (uint4*)KH; uint4* dkl = (uint4*)KL;
            for (int i = tid; i < 1536; i += 256) { dkh[i] = gkh[i]; dkl[i] = gkl[i]; }
            const uint4* gvh = (const uint4*)(g_Vh + (size_t)(h*128 + (k0>>4)) * 1024);
            const uint4* gvl = (const uint4*)(g_Vl + (size_t)(h*128 + (k0>>4)) * 1024);
            uint4* dvh = (uint4*)VH; uint4* dvl = (uint4*)VL;
            for (int i = tid; i < 1024; i += 256) { dvh[i] = gvh[i]; dvl[i] = gvl[i]; }
        }
        __syncthreads();

        if (k0 <= wrow0 + 15) {
            float S[8][4];
            #pragma unroll
            for (int nt = 0; nt < 8; nt++)
                #pragma unroll
                for (int r = 0; r < 4; r++) S[nt][r] = 0.f;

            #pragma unroll
            for (int kt = 0; kt < 12; kt++) {
                uint4 qh = *(const uint4*)&QH[wid * 1536 + kt * 128 + lane * 4];
                uint4 ql = *(const uint4*)&QL[wid * 1536 + kt * 128 + lane * 4];
                #pragma unroll
                for (int nt = 0; nt < 8; nt++) {
                    uint2 kh = *(const uint2*)&KH[(nt * 12 + kt) * 64 + lane * 2];
                    uint2 kl = *(const uint2*)&KL[(nt * 12 + kt) * 64 + lane * 2];
                    mma16(S[nt], qh, kh);
                    mma16(S[nt], qh, kl);
                    mma16(S[nt], ql, kh);
                }
            }

            if (k0 + 63 > wrow0) {
                const int row0 = wrow0 + g, row1 = row0 + 8;
                #pragma unroll
                for (int nt = 0; nt < 8; nt++) {
                    int col = k0 + nt * 8 + 2 * q;
                    if (col     > row0) S[nt][0] = -1e30f;
                    if (col + 1 > row0) S[nt][1] = -1e30f;
                    if (col     > row1) S[nt][2] = -1e30f;
                    if (col + 1 > row1) S[nt][3] = -1e30f;
                }
            }

            float rm0 = -1e30f, rm1 = -1e30f;
            #pragma unroll
            for (int nt = 0; nt < 8; nt++) {
                rm0 = fmaxf(rm0, fmaxf(S[nt][0], S[nt][1]));
                rm1 = fmaxf(rm1, fmaxf(S[nt][2], S[nt][3]));
            }
            rm0 = fmaxf(rm0, __shfl_xor_sync(0xffffffffu, rm0, 1));
            rm0 = fmaxf(rm0, __shfl_xor_sync(0xffffffffu, rm0, 2));
            rm1 = fmaxf(rm1, __shfl_xor_sync(0xffffffffu, rm1, 1));
            rm1 = fmaxf(rm1, __shfl_xor_sync(0xffffffffu, rm1, 2));

            float mn0 = fmaxf(m0, rm0), mn1 = fmaxf(m1, rm1);
            float a0 = __expf(m0 - mn0), a1 = __expf(m1 - mn1);

            unsigned PH[8], PL[8], P8H[8], P8L[8];
            float s0 = 0.f, s1 = 0.f;
            #pragma unroll
            for (int nt = 0; nt < 8; nt++) {
                float p00 = __expf(S[nt][0] - mn0);
                float p01 = __expf(S[nt][1] - mn0);
                float p10 = __expf(S[nt][2] - mn1);
                float p11 = __expf(S[nt][3] - mn1);
                s0 += p00 + p01; s1 += p10 + p11;
                split2(p00, p01, PH[nt], PL[nt]);
                split2(p10, p11, P8H[nt], P8L[nt]);
            }
            s0 += __shfl_xor_sync(0xffffffffu, s0, 1);
            s0 += __shfl_xor_sync(0xffffffffu, s0, 2);
            s1 += __shfl_xor_sync(0xffffffffu, s1, 1);
            s1 += __shfl_xor_sync(0xffffffffu, s1, 2);

            l0 = l0 * a0 + s0; l1 = l1 * a1 + s1;
            m0 = mn0; m1 = mn1;

            #pragma unroll
            for (int nt = 0; nt < 16; nt++) {
                O[nt][0] *= a0; O[nt][1] *= a0;
                O[nt][2] *= a1; O[nt][3] *= a1;
            }

            #pragma unroll
            for (int kt2 = 0; kt2 < 4; kt2++) {
                uint4 ah = make_uint4(PH[2*kt2], P8H[2*kt2], PH[2*kt2+1], P8H[2*kt2+1]);
                uint4 al = make_uint4(PL[2*kt2], P8L[2*kt2], PL[2*kt2+1], P8L[2*kt2+1]);
                #pragma unroll
                for (int nt = 0; nt < 16; nt++) {
                    uint2 vh = *(const uint2*)&VH[(kt2 * 16 + nt) * 64 + lane * 2];
                    uint2 vl = *(const uint2*)&VL[(kt2 * 16 + nt) * 64 + lane * 2];
                    mma16(O[nt], ah, vh);
                    mma16(O[nt], ah, vl);
                    mma16(O[nt], al, vh);
                }
            }
        }
        __syncthreads();
    }

    const float inv0 = __fdividef(1.f, l0), inv1 = __fdividef(1.f, l1);
    const int row0 = wrow0 + g;
    #pragma unroll
    for (int nt = 0; nt < 16; nt++) {
        const int col = h * DV + nt * 8 + 2 * q;
        *(float2*)&g_attn[(size_t)row0 * (NH * DV) + col] =
            make_float2(O[nt][0] * inv0, O[nt][1] * inv0);
        *(float2*)&g_attn[(size_t)(row0 + 8) * (NH * DV) + col] =
            make_float2(O[nt][2] * inv1, O[nt][3] * inv1);
    }
}

extern "C" void kernel_launch(void* const* d_in, const int* in_sizes, int n_in,
                              void* d_out, int out_size)
{
    const float* hs       = (const float*)d_in[0];
    const void*  pos_ids  = d_in[1];
    const float* q_a_w    = (const float*)d_in[2];
    const float* q_a_ln_w = (const float*)d_in[3];
    const float* q_b_w    = (const float*)d_in[4];
    const float* kv_a_w   = (const float*)d_in[5];
    const float* kv_a_ln_w= (const float*)d_in[6];
    const float* kv_b_w   = (const float*)d_in[7];
    const float* o_w      = (const float*)d_in[8];
    float*       out      = (float*)d_out;

    float *p_qa, *p_q, *p_kva, *p_kvb, *p_attn;
    cudaGetSymbolAddress((void**)&p_qa,   g_qa);
    cudaGetSymbolAddress((void**)&p_q,    g_q);
    cudaGetSymbolAddress((void**)&p_kva,  g_kva);
    cudaGetSymbolAddress((void**)&p_kvb,  g_kvb);
    cudaGetSymbolAddress((void**)&p_attn, g_attn);

    cudaFuncSetAttribute(flash_kernel,
                         cudaFuncAttributeMaxDynamicSharedMemorySize,
                         (int)FLASH_SMEM_BYTES);

    gemm_fp16x3_kernel<<<dim3(QR / 128, S_LEN / 128), 256>>>(
        hs, HID, q_a_w, p_qa, QR, HID);
    rmsnorm_kernel<<<S_LEN, 256>>>(p_qa, q_a_ln_w, QR, QR);
    gemm_fp16x3_kernel<<<dim3(NH * DQK / 128, S_LEN / 128), 256>>>(
        p_qa, QR, q_b_w, p_q, NH * DQK, QR);
    gemm_fp16x3_kernel<<<dim3((KVR + DR + 127) / 128, S_LEN / 128), 256>>>(
        hs, HID, kv_a_w, p_kva, KVR + DR, HID);
    rmsnorm_kernel<<<S_LEN, 256>>>(p_kva, kv_a_ln_w, KVR + DR, KVR);
    gemm_fp16x3_kernel<<<dim3(NH * (DN + DV) / 128, S_LEN / 128), 256>>>(
        p_kva, KVR + DR, kv_b_w, p_kvb, NH * (DN + DV), KVR);
    assemble_kernel<<<S_LEN / 2, 256>>>(pos_ids);
    flash_kernel<<<256, 256, FLASH_SMEM_BYTES>>>();
    gemm_fp16x3_kernel<<<dim3(HID / 128, S_LEN / 128), 256>>>(
        p_attn, NH * DV, o_w, out, HID, HID);
}

// round 7
// speedup vs baseline: 3.7108x; 1.3439x over previous
#include <cuda_runtime.h>
#include <cuda_fp16.h>
#include <cstdint>

constexpr int S_LEN = 2048, HID = 2048, NH = 16, QR = 1536, KVR = 512;
constexpr int DN = 128, DR = 64, DQK = 192, DV = 128;
constexpr float EPS = 1e-6f;

// fp32 intermediates
__device__ float g_qa [S_LEN * QR];
__device__ float g_q  [S_LEN * NH * DQK];
__device__ float g_kva[S_LEN * (KVR + DR)];
__device__ float g_kvb[S_LEN * NH * (DN + DV)];

// flash fragment arrays (hi/lo)
__device__ unsigned g_Qh[NH * (S_LEN/16) * 12 * 128];
__device__ unsigned g_Ql[NH * (S_LEN/16) * 12 * 128];
__device__ unsigned g_Kh[NH * (S_LEN/8)  * 12 * 64];
__device__ unsigned g_Kl[NH * (S_LEN/8)  * 12 * 64];
__device__ unsigned g_Vh[NH * (S_LEN/16) * 16 * 64];
__device__ unsigned g_Vl[NH * (S_LEN/16) * 16 * 64];

// GEMM operand planes: A layout [M/16][K/16][128], B layout [N/8][K/16][64]
__device__ unsigned g_AhsH [2097152], g_AhsL [2097152];  // hs       2048x2048
__device__ unsigned g_AqaH [1572864], g_AqaL [1572864];  // qa_norm  2048x1536
__device__ unsigned g_AkvH [524288],  g_AkvL [524288];   // kva_norm 2048x512
__device__ unsigned g_AatH [2097152], g_AatL [2097152];  // attn     2048x2048
__device__ unsigned g_BqaH [1572864], g_BqaL [1572864];  // q_a_w  1536x2048
__device__ unsigned g_BqbH [2359296], g_BqbL [2359296];  // q_b_w  3072x1536
__device__ unsigned g_BkaH [655360],  g_BkaL [655360];   // kv_a_w 640(pad)x2048
__device__ unsigned g_BkbH [1048576], g_BkbL [1048576];  // kv_b_w 4096x512
__device__ unsigned g_BowH [2097152], g_BowL [2097152];  // o_w    2048x2048

__device__ __forceinline__ void split2(float x0, float x1,
                                       unsigned& hi, unsigned& lo) {
    __half h0 = __float2half_rn(x0), h1 = __float2half_rn(x1);
    __half l0 = __float2half_rn(x0 - __half2float(h0));
    __half l1 = __float2half_rn(x1 - __half2float(h1));
    hi = (unsigned)__half_as_ushort(h0) | ((unsigned)__half_as_ushort(h1) << 16);
    lo = (unsigned)__half_as_ushort(l0) | ((unsigned)__half_as_ushort(l1) << 16);
}

__device__ __forceinline__ void mma16(float* c, const uint4& a, const uint2& b) {
    asm volatile(
        "mma.sync.aligned.m16n8k16.row.col.f32.f16.f16.f32 "
        "{%0,%1,%2,%3}, {%4,%5,%6,%7}, {%8,%9}, {%0,%1,%2,%3};"
        : "+f"(c[0]), "+f"(c[1]), "+f"(c[2]), "+f"(c[3])
        : "r"(a.x), "r"(a.y), "r"(a.z), "r"(a.w), "r"(b.x), "r"(b.y));
}

__device__ __forceinline__ void cpa16(uint32_t dst, const unsigned* src) {
    asm volatile("cp.async.cg.shared.global [%0], [%1], 16;"
                 :: "r"(dst), "l"(src) : "memory");
}

// ---------------------------------------------------------------------------
// Conversion kernels: fp32 row-major -> hi/lo fragment-permuted planes
// ---------------------------------------------------------------------------
__global__ void __launch_bounds__(256) convA_kernel(
    const float* __restrict__ X, unsigned* __restrict__ Ph,
    unsigned* __restrict__ Pl, int K)
{
    size_t id = (size_t)blockIdx.x * 256 + threadIdx.x;
    int m = (int)(id / (K >> 1));
    int d = (int)(id % (K >> 1)) * 2;
    float2 v = *(const float2*)&X[(size_t)m * K + d];
    unsigned hi, lo; split2(v.x, v.y, hi, lo);
    size_t off = ((size_t)(m >> 4) * (K >> 4) + (d >> 4)) * 128
               + ((m & 7) * 4 + ((d & 7) >> 1)) * 4
               + ((d >> 3) & 1) * 2 + ((m >> 3) & 1);
    Ph[off] = hi; Pl[off] = lo;
}

__global__ void __launch_bounds__(256) convB_kernel(
    const float* __restrict__ W, unsigned* __restrict__ Ph,
    unsigned* __restrict__ Pl, int N, int K)
{
    size_t id = (size_t)blockIdx.x * 256 + threadIdx.x;
    int n = (int)(id / (K >> 1));
    int d = (int)(id % (K >> 1)) * 2;
    float v0 = 0.f, v1 = 0.f;
    if (n < N) { float2 v = *(const float2*)&W[(size_t)n * K + d]; v0 = v.x; v1 = v.y; }
    unsigned hi, lo; split2(v0, v1, hi, lo);
    size_t off = ((size_t)(n >> 3) * (K >> 4) + (d >> 4)) * 64
               + ((n & 7) * 4 + ((d & 7) >> 1)) * 2 + ((d >> 3) & 1);
    Ph[off] = hi; Pl[off] = lo;
}

// ---------------------------------------------------------------------------
// GEMM on pre-converted planes: C[M,N] = A * B^T (fp16x3, HMMA)
// CTA 128x128, BK=32, cp.async double buffer.
// ---------------------------------------------------------------------------
__global__ void __launch_bounds__(256, 2) gemm_fr_kernel(
    const unsigned* __restrict__ Ah, const unsigned* __restrict__ Al,
    const unsigned* __restrict__ Bh, const unsigned* __restrict__ Bl,
    float* __restrict__ C, int N, int K)
{
    __shared__ unsigned sm[2][4][2048];   // [stage][Ah,Al,Bh,Bl][...]

    const int tid = threadIdx.x, lane = tid & 31, warp = tid >> 5;
    const int wm = warp >> 2, wn = warp & 3;
    const int m0t = blockIdx.y * 8, n0t = blockIdx.x * 16;
    const int KT = K >> 4;

    // per-thread copy slots (two uint4 per plane)
    const int f0 = tid, f1 = tid + 256;
    const int aM0 = f0 >> 6, aK0 = (f0 & 63) >> 5, aW0 = f0 & 31;
    const int aM1 = f1 >> 6, aK1 = (f1 & 63) >> 5, aW1 = f1 & 31;
    const size_t aS0 = ((size_t)(m0t + aM0) * KT + aK0) * 128 + aW0 * 4;
    const size_t aS1 = ((size_t)(m0t + aM1) * KT + aK1) * 128 + aW1 * 4;
    const int aD0 = (aM0 * 2 + aK0) * 128 + aW0 * 4;
    const int aD1 = (aM1 * 2 + aK1) * 128 + aW1 * 4;
    const int bN0 = f0 >> 5, bK0 = (f0 & 31) >> 4, bW0 = f0 & 15;
    const int bN1 = f1 >> 5, bK1 = (f1 & 31) >> 4, bW1 = f1 & 15;
    const size_t bS0 = ((size_t)(n0t + bN0) * KT + bK0) * 64 + bW0 * 4;
    const size_t bS1 = ((size_t)(n0t + bN1) * KT + bK1) * 64 + bW1 * 4;
    const int bD0 = (bN0 * 2 + bK0) * 64 + bW0 * 4;
    const int bD1 = (bN1 * 2 + bK1) * 64 + bW1 * 4;

    const uint32_t sb = (uint32_t)__cvta_generic_to_shared(&sm[0][0][0]);
    auto issue = [&](int c, int st) {
        const size_t ao = (size_t)c * 256, bo = (size_t)c * 128;
        const uint32_t s0 = sb + (uint32_t)(st * 4) * 8192;
        cpa16(s0 + aD0 * 4,          Ah + aS0 + ao);
        cpa16(s0 + aD1 * 4,          Ah + aS1 + ao);
        cpa16(s0 + 8192  + aD0 * 4,  Al + aS0 + ao);
        cpa16(s0 + 8192  + aD1 * 4,  Al + aS1 + ao);
        cpa16(s0 + 16384 + bD0 * 4,  Bh + bS0 + bo);
        cpa16(s0 + 16384 + bD1 * 4,  Bh + bS1 + bo);
        cpa16(s0 + 24576 + bD0 * 4,  Bl + bS0 + bo);
        cpa16(s0 + 24576 + bD1 * 4,  Bl + bS1 + bo);
        asm volatile("cp.async.commit_group;" ::: "memory");
    };

    float acc[4][4][4];
    #pragma unroll
    for (int i = 0; i < 4; i++)
        #pragma unroll
        for (int j = 0; j < 4; j++)
            #pragma unroll
            for (int r = 0; r < 4; r++) acc[i][j][r] = 0.f;

    const int nc = K >> 5;
    issue(0, 0);

    for (int c = 0; c < nc; c++) {
        const int s = c & 1;
        if (c + 1 < nc) {
            issue(c + 1, s ^ 1);
            asm volatile("cp.async.wait_group 1;" ::: "memory");
        } else {
            asm volatile("cp.async.wait_group 0;" ::: "memory");
        }
        __syncthreads();

        #pragma unroll
        for (int kt = 0; kt < 2; kt++) {
            uint4 a_h[4], a_l[4];
            #pragma unroll
            for (int i = 0; i < 4; i++) {
                int off = ((wm * 4 + i) * 2 + kt) * 128 + lane * 4;
                a_h[i] = *(const uint4*)&sm[s][0][off];
                a_l[i] = *(const uint4*)&sm[s][1][off];
            }
            #pragma unroll
            for (int jp = 0; jp < 2; jp++) {
                uint2 b_h[2], b_l[2];
                #pragma unroll
                for (int jj = 0; jj < 2; jj++) {
                    int off = ((wn * 4 + jp * 2 + jj) * 2 + kt) * 64 + lane * 2;
                    b_h[jj] = *(const uint2*)&sm[s][2][off];
                    b_l[jj] = *(const uint2*)&sm[s][3][off];
                }
                #pragma unroll
                for (int jj = 0; jj < 2; jj++)
                    #pragma unroll
                    for (int i = 0; i < 4; i++)
                        mma16(acc[i][jp*2+jj], a_h[i], b_h[jj]);
                #pragma unroll
                for (int jj = 0; jj < 2; jj++)
                    #pragma unroll
                    for (int i = 0; i < 4; i++)
                        mma16(acc[i][jp*2+jj], a_h[i], b_l[jj]);
                #pragma unroll
                for (int jj = 0; jj < 2; jj++)
                    #pragma unroll
                    for (int i = 0; i < 4; i++)
                        mma16(acc[i][jp*2+jj], a_l[i], b_h[jj]);
            }
        }
        __syncthreads();
    }

    const int g = lane >> 2, q = lane & 3;
    const int m0 = blockIdx.y * 128, n0 = blockIdx.x * 128;
    #pragma unroll
    for (int i = 0; i < 4; i++) {
        const int row = m0 + wm * 64 + i * 16 + g;
        #pragma unroll
        for (int j = 0; j < 4; j++) {
            const int colb = n0 + wn * 32 + j * 8;
            if (colb < N) {
                const int col = colb + 2 * q;
                *(float2*)&C[(size_t)row * N + col] =
                    make_float2(acc[i][j][0], acc[i][j][1]);
                *(float2*)&C[(size_t)(row + 8) * N + col] =
                    make_float2(acc[i][j][2], acc[i][j][3]);
            }
        }
    }
}

// ---------------------------------------------------------------------------
// RMSNorm -> A-layout fp16 planes
// ---------------------------------------------------------------------------
__global__ void __launch_bounds__(256) rmsnormA_kernel(
    const float* __restrict__ x, const float* __restrict__ w,
    unsigned* __restrict__ Ph, unsigned* __restrict__ Pl, int ld, int n)
{
    const int row = blockIdx.x;
    const float* xr = x + (size_t)row * ld;
    float s = 0.f;
    for (int i = threadIdx.x; i < n; i += 256) { float v = xr[i]; s += v * v; }
    __shared__ float red[8];
    #pragma unroll
    for (int o = 16; o; o >>= 1) s += __shfl_xor_sync(0xffffffffu, s, o);
    if ((threadIdx.x & 31) == 0) red[threadIdx.x >> 5] = s;
    __syncthreads();
    if (threadIdx.x < 32) {
        float v = (threadIdx.x < 8) ? red[threadIdx.x] : 0.f;
        #pragma unroll
        for (int o = 4; o; o >>= 1) v += __shfl_xor_sync(0xffffffffu, v, o);
        if (threadIdx.x == 0) red[0] = v;
    }
    __syncthreads();
    const float r = rsqrtf(red[0] / (float)n + EPS);
    for (int dp = threadIdx.x; dp < (n >> 1); dp += 256) {
        int d = dp * 2;
        float v0 = w[d] * xr[d] * r, v1 = w[d + 1] * xr[d + 1] * r;
        unsigned hi, lo; split2(v0, v1, hi, lo);
        size_t off = ((size_t)(row >> 4) * (n >> 4) + (d >> 4)) * 128
                   + ((row & 7) * 4 + ((d & 7) >> 1)) * 4
                   + ((d >> 3) & 1) * 2 + ((row >> 3) & 1);
        Ph[off] = hi; Pl[off] = lo;
    }
}

// ---------------------------------------------------------------------------
// Assemble: RoPE + flash fragment layouts (unchanged from R5)
// ---------------------------------------------------------------------------
__global__ void __launch_bounds__(256) assemble_kernel(
    const void* __restrict__ pos_ids)
{
    const int b = blockIdx.x, t0 = 2 * b, tid = threadIdx.x;
    __shared__ float cs[2][DR], sn[2][DR], kr[2][DR];
    __shared__ float posv[2];

    if (tid < 2) {
        const int* p32 = (const int*)pos_ids;
        int t = t0 + tid;
        long long pv = (p32[1] == 0) ? ((const long long*)pos_ids)[t]
                                     : (long long)p32[t];
        posv[tid] = (float)pv;
    }
    __syncthreads();
    if (tid < 128) {
        int tok = tid >> 6, i = tid & 63, j = i & 31;
        double e = -((double)(2 * j) / 64.0) * 13.287712379549449;
        float ang = posv[tok] * (float)exp2(e);
        cs[tok][i] = cosf(ang); sn[tok][i] = sinf(ang);
    }
    __syncthreads();
    if (tid < 128) {
        int tok = tid >> 6, i = tid & 63;
        const float* kx = g_kva + (size_t)(t0 + tok) * (KVR + DR) + KVR;
        kr[tok][i] = (i < 32) ? kx[i] * cs[tok][i] - kx[i + 32] * sn[tok][i]
                              : kx[i] * cs[tok][i] + kx[i - 32] * sn[tok][i];
    }
    __syncthreads();

    const float scale = rsqrtf((float)DQK);

    for (int h = 0; h < NH; h++) {
        for (int w = tid; w < 192; w += 256) {          // Q
            int tok = w / 96, pp = w % 96, d = 2 * pp;
            int t = t0 + tok;
            const float* qrow = g_q + (size_t)t * (NH * DQK) + h * DQK;
            float v0, v1;
            if (d < DN) { v0 = qrow[d]; v1 = qrow[d + 1]; }
            else {
                int i = d - DN;
                if (i < 32) {
                    v0 = qrow[d]   * cs[tok][i]   - qrow[d + 32] * sn[tok][i];
                    v1 = qrow[d+1] * cs[tok][i+1] - qrow[d + 33] * sn[tok][i+1];
                } else {
                    v0 = qrow[d]   * cs[tok][i]   + qrow[d - 32] * sn[tok][i];
                    v1 = qrow[d+1] * cs[tok][i+1] + qrow[d - 31] * sn[tok][i+1];
                }
            }
            v0 *= scale; v1 *= scale;
            unsigned hi, lo; split2(v0, v1, hi, lo);
            int mt = t >> 4, r = t & 15;
            size_t off = ((size_t)(h * 128 + mt) * 12 + (d >> 4)) * 128
                       + ((r & 7) * 4 + ((d & 7) >> 1)) * 4
                       + (((d >> 3) & 1) * 2 + (r >> 3));
            g_Qh[off] = hi; g_Ql[off] = lo;
        }
        for (int w = tid; w < 192; w += 256) {          // K
            int tok = w / 96, pp = w % 96, d = 2 * pp;
            int t = t0 + tok;
            const float* kvrow = g_kvb + (size_t)t * (NH*(DN+DV)) + h * (DN+DV);
            float v0, v1;
            if (d < DN) { v0 = kvrow[d]; v1 = kvrow[d + 1]; }
            else        { v0 = kr[tok][d - DN]; v1 = kr[tok][d - DN + 1]; }
            unsigned hi, lo; split2(v0, v1, hi, lo);
            int nt = t >> 3, n = t & 7;
            size_t off = ((size_t)(h * 256 + nt) * 12 + (d >> 4)) * 64
                       + (n * 4 + ((d & 7) >> 1)) * 2 + ((d >> 3) & 1);
            g_Kh[off] = hi; g_Kl[off] = lo;
        }
        if (tid < 128) {                                 // V
            int d = tid;
            float v0 = g_kvb[(size_t)t0     * (NH*(DN+DV)) + h*(DN+DV) + DN + d];
            float v1 = g_kvb[(size_t)(t0+1) * (NH*(DN+DV)) + h*(DN+DV) + DN + d];
            unsigned hi, lo; split2(v0, v1, hi, lo);
            size_t off = ((size_t)(h * 128 + (t0 >> 4)) * 16 + (d >> 3)) * 64
                       + ((d & 7) * 4 + ((t0 & 7) >> 1)) * 2 + ((t0 >> 3) & 1);
            g_Vh[off] = hi; g_Vl[off] = lo;
        }
    }
}

// ---------------------------------------------------------------------------
// Flash attention (fp16x3 mma); epilogue writes A-layout attn planes.
// ---------------------------------------------------------------------------
constexpr int FLASH_SMEM_U32 = 2*12288 + 2*6144 + 2*4096;
constexpr size_t FLASH_SMEM_BYTES = FLASH_SMEM_U32 * 4;

__global__ void __launch_bounds__(256) flash_kernel()
{
    const int bx = blockIdx.x;
    const int qt = 15 - (bx >> 4);
    const int h  = bx & 15;
    const int q0 = qt * 128;
    const int tid = threadIdx.x, wid = tid >> 5, lane = tid & 31;
    const int g = lane >> 2, q = lane & 3;

    extern __shared__ unsigned smu[];
    unsigned* QH = smu;
    unsigned* QL = QH + 12288;
    unsigned* KH = QL + 12288;
    unsigned* KL = KH + 6144;
    unsigned* VH = KL + 6144;
    unsigned* VL = VH + 4096;

    {
        const uint4* gh = (const uint4*)(g_Qh + (size_t)(h * 128 + qt * 8) * 1536);
        const uint4* gl = (const uint4*)(g_Ql + (size_t)(h * 128 + qt * 8) * 1536);
        uint4* dh = (uint4*)QH; uint4* dl = (uint4*)QL;
        for (int i = tid; i < 3072; i += 256) { dh[i] = gh[i]; dl[i] = gl[i]; }
    }

    float O[16][4];
    #pragma unroll
    for (int nt = 0; nt < 16; nt++)
        #pragma unroll
        for (int r = 0; r < 4; r++) O[nt][r] = 0.f;
    float m0 = -1e30f, m1 = -1e30f, l0 = 0.f, l1 = 0.f;

    const int wrow0 = q0 + wid * 16;
    const int niter = 2 * (qt + 1);

    for (int it = 0; it < niter; it++) {
        const int k0 = it * 64;
        {
            const uint4* gkh = (const uint4*)(g_Kh + (size_t)(h*256 + (k0>>3)) * 768);
            const uint4* gkl = (const uint4*)(g_Kl + (size_t)(h*256 + (k0>>3)) * 768);
            uint4* dkh = (uint4*)KH; uint4* dkl = (uint4*)KL;
            for (int i = tid; i < 1536; i += 256) { dkh[i] = gkh[i]; dkl[i] = gkl[i]; }
            const uint4* gvh = (const uint4*)(g_Vh + (size_t)(h*128 + (k0>>4)) * 1024);
            const uint4* gvl = (const uint4*)(g_Vl + (size_t)(h*128 + (k0>>4)) * 1024);
            uint4* dvh = (uint4*)VH; uint4* dvl = (uint4*)VL;
            for (int i = tid; i < 1024; i += 256) { dvh[i] = gvh[i]; dvl[i] = gvl[i]; }
        }
        __syncthreads();

        if (k0 <= wrow0 + 15) {
            float S[8][4];
            #pragma unroll
            for (int nt = 0; nt < 8; nt++)
                #pragma unroll
                for (int r = 0; r < 4; r++) S[nt][r] = 0.f;

            #pragma unroll
            for (int kt = 0; kt < 12; kt++) {
                uint4 qh = *(const uint4*)&QH[wid * 1536 + kt * 128 + lane * 4];
                uint4 ql = *(const uint4*)&QL[wid * 1536 + kt * 128 + lane * 4];
                #pragma unroll
                for (int nt = 0; nt < 8; nt++) {
                    uint2 kh = *(const uint2*)&KH[(nt * 12 + kt) * 64 + lane * 2];
                    uint2 kl = *(const uint2*)&KL[(nt * 12 + kt) * 64 + lane * 2];
                    mma16(S[nt], qh, kh);
                    mma16(S[nt], qh, kl);
                    mma16(S[nt], ql, kh);
                }
            }

            if (k0 + 63 > wrow0) {
                const int row0 = wrow0 + g, row1 = row0 + 8;
                #pragma unroll
                for (int nt = 0; nt < 8; nt++) {
                    int col = k0 + nt * 8 + 2 * q;
                    if (col     > row0) S[nt][0] = -1e30f;
                    if (col + 1 > row0) S[nt][1] = -1e30f;
                    if (col     > row1) S[nt][2] = -1e30f;
                    if (col + 1 > row1) S[nt][3] = -1e30f;
                }
            }

            float rm0 = -1e30f, rm1 = -1e30f;
            #pragma unroll
            for (int nt = 0; nt < 8; nt++) {
                rm0 = fmaxf(rm0, fmaxf(S[nt][0], S[nt][1]));
                rm1 = fmaxf(rm1, fmaxf(S[nt][2], S[nt][3]));
            }
            rm0 = fmaxf(rm0, __shfl_xor_sync(0xffffffffu, rm0, 1));
            rm0 = fmaxf(rm0, __shfl_xor_sync(0xffffffffu, rm0, 2));
            rm1 = fmaxf(rm1, __shfl_xor_sync(0xffffffffu, rm1, 1));
            rm1 = fmaxf(rm1, __shfl_xor_sync(0xffffffffu, rm1, 2));

            float mn0 = fmaxf(m0, rm0), mn1 = fmaxf(m1, rm1);
            float a0 = __expf(m0 - mn0), a1 = __expf(m1 - mn1);

            unsigned PH[8], PL[8], P8H[8], P8L[8];
            float s0 = 0.f, s1 = 0.f;
            #pragma unroll
            for (int nt = 0; nt < 8; nt++) {
                float p00 = __expf(S[nt][0] - mn0);
                float p01 = __expf(S[nt][1] - mn0);
                float p10 = __expf(S[nt][2] - mn1);
                float p11 = __expf(S[nt][3] - mn1);
                s0 += p00 + p01; s1 += p10 + p11;
                split2(p00, p01, PH[nt], PL[nt]);
                split2(p10, p11, P8H[nt], P8L[nt]);
            }
            s0 += __shfl_xor_sync(0xffffffffu, s0, 1);
            s0 += __shfl_xor_sync(0xffffffffu, s0, 2);
            s1 += __shfl_xor_sync(0xffffffffu, s1, 1);
            s1 += __shfl_xor_sync(0xffffffffu, s1, 2);

            l0 = l0 * a0 + s0; l1 = l1 * a1 + s1;
            m0 = mn0; m1 = mn1;

            #pragma unroll
            for (int nt = 0; nt < 16; nt++) {
                O[nt][0] *= a0; O[nt][1] *= a0;
                O[nt][2] *= a1; O[nt][3] *= a1;
            }

            #pragma unroll
            for (int kt2 = 0; kt2 < 4; kt2++) {
                uint4 ah = make_uint4(PH[2*kt2], P8H[2*kt2], PH[2*kt2+1], P8H[2*kt2+1]);
                uint4 al = make_uint4(PL[2*kt2], P8L[2*kt2], PL[2*kt2+1], P8L[2*kt2+1]);
                #pragma unroll
                for (int nt = 0; nt < 16; nt++) {
                    uint2 vh = *(const uint2*)&VH[(kt2 * 16 + nt) * 64 + lane * 2];
                    uint2 vl = *(const uint2*)&VL[(kt2 * 16 + nt) * 64 + lane * 2];
                    mma16(O[nt], ah, vh);
                    mma16(O[nt], ah, vl);
                    mma16(O[nt], al, vh);
                }
            }
        }
        __syncthreads();
    }

    // epilogue -> A-layout attn planes (M=2048, K=2048 => 128 k-tiles)
    const float inv0 = __fdividef(1.f, l0), inv1 = __fdividef(1.f, l1);
    const int row0 = wrow0 + g;
    const size_t baseRow = (size_t)(row0 >> 4) * 128;
    #pragma unroll
    for (int nt = 0; nt < 16; nt++) {
        const int ktv = h * 8 + (nt >> 1);
        const size_t off = (baseRow + ktv) * 128 + lane * 4 + (nt & 1) * 2;
        unsigned hi, lo;
        split2(O[nt][0] * inv0, O[nt][1] * inv0, hi, lo);
        g_AatH[off] = hi; g_AatL[off] = lo;
        split2(O[nt][2] * inv1, O[nt][3] * inv1, hi, lo);
        g_AatH[off + 1] = hi; g_AatL[off + 1] = lo;
    }
}

// ---------------------------------------------------------------------------
extern "C" void kernel_launch(void* const* d_in, const int* in_sizes, int n_in,
                              void* d_out, int out_size)
{
    const float* hs       = (const float*)d_in[0];
    const void*  pos_ids  = d_in[1];
    const float* q_a_w    = (const float*)d_in[2];
    const float* q_a_ln_w = (const float*)d_in[3];
    const float* q_b_w    = (const float*)d_in[4];
    const float* kv_a_w   = (const float*)d_in[5];
    const float* kv_a_ln_w= (const float*)d_in[6];
    const float* kv_b_w   = (const float*)d_in[7];
    const float* o_w      = (const float*)d_in[8];
    float*       out      = (float*)d_out;

    float *p_qa, *p_q, *p_kva, *p_kvb;
    cudaGetSymbolAddress((void**)&p_qa,  g_qa);
    cudaGetSymbolAddress((void**)&p_q,   g_q);
    cudaGetSymbolAddress((void**)&p_kva, g_kva);
    cudaGetSymbolAddress((void**)&p_kvb, g_kvb);
    unsigned *AhsH,*AhsL,*AqaH,*AqaL,*AkvH,*AkvL,*AatH,*AatL;
    unsigned *BqaH,*BqaL,*BqbH,*BqbL,*BkaH,*BkaL,*BkbH,*BkbL,*BowH,*BowL;
    cudaGetSymbolAddress((void**)&AhsH, g_AhsH); cudaGetSymbolAddress((void**)&AhsL, g_AhsL);
    cudaGetSymbolAddress((void**)&AqaH, g_AqaH); cudaGetSymbolAddress((void**)&AqaL, g_AqaL);
    cudaGetSymbolAddress((void**)&AkvH, g_AkvH); cudaGetSymbolAddress((void**)&AkvL, g_AkvL);
    cudaGetSymbolAddress((void**)&AatH, g_AatH); cudaGetSymbolAddress((void**)&AatL, g_AatL);
    cudaGetSymbolAddress((void**)&BqaH, g_BqaH); cudaGetSymbolAddress((void**)&BqaL, g_BqaL);
    cudaGetSymbolAddress((void**)&BqbH, g_BqbH); cudaGetSymbolAddress((void**)&BqbL, g_BqbL);
    cudaGetSymbolAddress((void**)&BkaH, g_BkaH); cudaGetSymbolAddress((void**)&BkaL, g_BkaL);
    cudaGetSymbolAddress((void**)&BkbH, g_BkbH); cudaGetSymbolAddress((void**)&BkbL, g_BkbL);
    cudaGetSymbolAddress((void**)&BowH, g_BowH); cudaGetSymbolAddress((void**)&BowL, g_BowL);

    cudaFuncSetAttribute(flash_kernel,
                         cudaFuncAttributeMaxDynamicSharedMemorySize,
                         (int)FLASH_SMEM_BYTES);

    // conversions
    convA_kernel<<<8192, 256>>>(hs, AhsH, AhsL, HID);
    convB_kernel<<<6144, 256>>>(q_a_w, BqaH, BqaL, QR, HID);
    convB_kernel<<<9216, 256>>>(q_b_w, BqbH, BqbL, NH * DQK, QR);
    convB_kernel<<<2560, 256>>>(kv_a_w, BkaH, BkaL, KVR + DR, HID);
    convB_kernel<<<4096, 256>>>(kv_b_w, BkbH, BkbL, NH * (DN + DV), KVR);
    convB_kernel<<<8192, 256>>>(o_w, BowH, BowL, HID, HID);

    // q chain + kv chain
    gemm_fr_kernel<<<dim3(12, 16), 256>>>(AhsH, AhsL, BqaH, BqaL, p_qa, QR, HID);
    gemm_fr_kernel<<<dim3(5, 16), 256>>>(AhsH, AhsL, BkaH, BkaL, p_kva, KVR + DR, HID);
    rmsnormA_kernel<<<S_LEN, 256>>>(p_qa, q_a_ln_w, AqaH, AqaL, QR, QR);
    rmsnormA_kernel<<<S_LEN, 256>>>(p_kva, kv_a_ln_w, AkvH, AkvL, KVR + DR, KVR);
    gemm_fr_kernel<<<dim3(24, 16), 256>>>(AqaH, AqaL, BqbH, BqbL, p_q, NH * DQK, QR);
    gemm_fr_kernel<<<dim3(32, 16), 256>>>(AkvH, AkvL, BkbH, BkbL, p_kvb,
                                          NH * (DN + DV), KVR);
    assemble_kernel<<<S_LEN / 2, 256>>>(pos_ids);
    flash_kernel<<<256, 256, FLASH_SMEM_BYTES>>>();
    gemm_fr_kernel<<<dim3(16, 16), 256>>>(AatH, AatL, BowH, BowL, out, HID, HID);
}

// round 8
// speedup vs baseline: 5.0713x; 1.3666x over previous
#include <cuda_runtime.h>
#include <cuda_fp16.h>
#include <cstdint>

constexpr int S_LEN = 2048, HID = 2048, NH = 16, QR = 1536, KVR = 512;
constexpr int DN = 128, DR = 64, DQK = 192, DV = 128;
constexpr float EPS = 1e-6f;

__device__ float g_qa [S_LEN * QR];
__device__ float g_q  [S_LEN * NH * DQK];
__device__ float g_kva[S_LEN * (KVR + DR)];
__device__ float g_kvb[S_LEN * NH * (DN + DV)];

__device__ unsigned g_Qh[NH * (S_LEN/16) * 12 * 128];
__device__ unsigned g_Ql[NH * (S_LEN/16) * 12 * 128];
__device__ unsigned g_Kh[NH * (S_LEN/8)  * 12 * 64];
__device__ unsigned g_Kl[NH * (S_LEN/8)  * 12 * 64];
__device__ unsigned g_Vh[NH * (S_LEN/16) * 16 * 64];
__device__ unsigned g_Vl[NH * (S_LEN/16) * 16 * 64];

__device__ unsigned g_AhsH [2097152], g_AhsL [2097152];
__device__ unsigned g_AqaH [1572864], g_AqaL [1572864];
__device__ unsigned g_AkvH [524288],  g_AkvL [524288];
__device__ unsigned g_AatH [2097152], g_AatL [2097152];
__device__ unsigned g_BqaH [1572864], g_BqaL [1572864];
__device__ unsigned g_BqbH [2359296], g_BqbL [2359296];
__device__ unsigned g_BkaH [655360],  g_BkaL [655360];
__device__ unsigned g_BkbH [1048576], g_BkbL [1048576];
__device__ unsigned g_BowH [2097152], g_BowL [2097152];

__device__ __forceinline__ void split2(float x0, float x1,
                                       unsigned& hi, unsigned& lo) {
    __half h0 = __float2half_rn(x0), h1 = __float2half_rn(x1);
    __half l0 = __float2half_rn(x0 - __half2float(h0));
    __half l1 = __float2half_rn(x1 - __half2float(h1));
    hi = (unsigned)__half_as_ushort(h0) | ((unsigned)__half_as_ushort(h1) << 16);
    lo = (unsigned)__half_as_ushort(l0) | ((unsigned)__half_as_ushort(l1) << 16);
}

__device__ __forceinline__ void mma16(float* c, const uint4& a, const uint2& b) {
    asm volatile(
        "mma.sync.aligned.m16n8k16.row.col.f32.f16.f16.f32 "
        "{%0,%1,%2,%3}, {%4,%5,%6,%7}, {%8,%9}, {%0,%1,%2,%3};"
        : "+f"(c[0]), "+f"(c[1]), "+f"(c[2]), "+f"(c[3])
        : "r"(a.x), "r"(a.y), "r"(a.z), "r"(a.w), "r"(b.x), "r"(b.y));
}

__device__ __forceinline__ void cpa16(uint32_t dst, const void* src) {
    asm volatile("cp.async.cg.shared.global [%0], [%1], 16;"
                 :: "r"(dst), "l"(src) : "memory");
}

// ---------------------------------------------------------------------------
__global__ void __launch_bounds__(256) convA_kernel(
    const float* __restrict__ X, unsigned* __restrict__ Ph,
    unsigned* __restrict__ Pl, int K)
{
    size_t id = (size_t)blockIdx.x * 256 + threadIdx.x;
    int m = (int)(id / (K >> 1));
    int d = (int)(id % (K >> 1)) * 2;
    float2 v = *(const float2*)&X[(size_t)m * K + d];
    unsigned hi, lo; split2(v.x, v.y, hi, lo);
    size_t off = ((size_t)(m >> 4) * (K >> 4) + (d >> 4)) * 128
               + ((m & 7) * 4 + ((d & 7) >> 1)) * 4
               + ((d >> 3) & 1) * 2 + ((m >> 3) & 1);
    Ph[off] = hi; Pl[off] = lo;
}

__global__ void __launch_bounds__(256) convB_kernel(
    const float* __restrict__ W, unsigned* __restrict__ Ph,
    unsigned* __restrict__ Pl, int N, int K)
{
    size_t id = (size_t)blockIdx.x * 256 + threadIdx.x;
    int n = (int)(id / (K >> 1));
    int d = (int)(id % (K >> 1)) * 2;
    float v0 = 0.f, v1 = 0.f;
    if (n < N) { float2 v = *(const float2*)&W[(size_t)n * K + d]; v0 = v.x; v1 = v.y; }
    unsigned hi, lo; split2(v0, v1, hi, lo);
    size_t off = ((size_t)(n >> 3) * (K >> 4) + (d >> 4)) * 64
               + ((n & 7) * 4 + ((d & 7) >> 1)) * 2 + ((d >> 3) & 1);
    Ph[off] = hi; Pl[off] = lo;
}

// ---------------------------------------------------------------------------
__global__ void __launch_bounds__(256, 2) gemm_fr_kernel(
    const unsigned* __restrict__ Ah, const unsigned* __restrict__ Al,
    const unsigned* __restrict__ Bh, const unsigned* __restrict__ Bl,
    float* __restrict__ C, int N, int K)
{
    __shared__ unsigned sm[2][4][2048];

    const int tid = threadIdx.x, lane = tid & 31, warp = tid >> 5;
    const int wm = warp >> 2, wn = warp & 3;
    const int m0t = blockIdx.y * 8, n0t = blockIdx.x * 16;
    const int KT = K >> 4;

    const int f0 = tid, f1 = tid + 256;
    const int aM0 = f0 >> 6, aK0 = (f0 & 63) >> 5, aW0 = f0 & 31;
    const int aM1 = f1 >> 6, aK1 = (f1 & 63) >> 5, aW1 = f1 & 31;
    const size_t aS0 = ((size_t)(m0t + aM0) * KT + aK0) * 128 + aW0 * 4;
    const size_t aS1 = ((size_t)(m0t + aM1) * KT + aK1) * 128 + aW1 * 4;
    const int aD0 = (aM0 * 2 + aK0) * 128 + aW0 * 4;
    const int aD1 = (aM1 * 2 + aK1) * 128 + aW1 * 4;
    const int bN0 = f0 >> 5, bK0 = (f0 & 31) >> 4, bW0 = f0 & 15;
    const int bN1 = f1 >> 5, bK1 = (f1 & 31) >> 4, bW1 = f1 & 15;
    const size_t bS0 = ((size_t)(n0t + bN0) * KT + bK0) * 64 + bW0 * 4;
    const size_t bS1 = ((size_t)(n0t + bN1) * KT + bK1) * 64 + bW1 * 4;
    const int bD0 = (bN0 * 2 + bK0) * 64 + bW0 * 4;
    const int bD1 = (bN1 * 2 + bK1) * 64 + bW1 * 4;

    const uint32_t sb = (uint32_t)__cvta_generic_to_shared(&sm[0][0][0]);
    auto issue = [&](int c, int st) {
        const size_t ao = (size_t)c * 256, bo = (size_t)c * 128;
        const uint32_t s0 = sb + (uint32_t)(st * 4) * 8192;
        cpa16(s0 + aD0 * 4,          Ah + aS0 + ao);
        cpa16(s0 + aD1 * 4,          Ah + aS1 + ao);
        cpa16(s0 + 8192  + aD0 * 4,  Al + aS0 + ao);
        cpa16(s0 + 8192  + aD1 * 4,  Al + aS1 + ao);
        cpa16(s0 + 16384 + bD0 * 4,  Bh + bS0 + bo);
        cpa16(s0 + 16384 + bD1 * 4,  Bh + bS1 + bo);
        cpa16(s0 + 24576 + bD0 * 4,  Bl + bS0 + bo);
        cpa16(s0 + 24576 + bD1 * 4,  Bl + bS1 + bo);
        asm volatile("cp.async.commit_group;" ::: "memory");
    };

    float acc[4][4][4];
    #pragma unroll
    for (int i = 0; i < 4; i++)
        #pragma unroll
        for (int j = 0; j < 4; j++)
            #pragma unroll
            for (int r = 0; r < 4; r++) acc[i][j][r] = 0.f;

    const int nc = K >> 5;
    issue(0, 0);

    for (int c = 0; c < nc; c++) {
        const int s = c & 1;
        if (c + 1 < nc) {
            issue(c + 1, s ^ 1);
            asm volatile("cp.async.wait_group 1;" ::: "memory");
        } else {
            asm volatile("cp.async.wait_group 0;" ::: "memory");
        }
        __syncthreads();

        #pragma unroll
        for (int kt = 0; kt < 2; kt++) {
            uint4 a_h[4], a_l[4];
            #pragma unroll
            for (int i = 0; i < 4; i++) {
                int off = ((wm * 4 + i) * 2 + kt) * 128 + lane * 4;
                a_h[i] = *(const uint4*)&sm[s][0][off];
                a_l[i] = *(const uint4*)&sm[s][1][off];
            }
            #pragma unroll
            for (int jp = 0; jp < 2; jp++) {
                uint2 b_h[2], b_l[2];
                #pragma unroll
                for (int jj = 0; jj < 2; jj++) {
                    int off = ((wn * 4 + jp * 2 + jj) * 2 + kt) * 64 + lane * 2;
                    b_h[jj] = *(const uint2*)&sm[s][2][off];
                    b_l[jj] = *(const uint2*)&sm[s][3][off];
                }
                #pragma unroll
                for (int jj = 0; jj < 2; jj++)
                    #pragma unroll
                    for (int i = 0; i < 4; i++)
                        mma16(acc[i][jp*2+jj], a_h[i], b_h[jj]);
                #pragma unroll
                for (int jj = 0; jj < 2; jj++)
                    #pragma unroll
                    for (int i = 0; i < 4; i++)
                        mma16(acc[i][jp*2+jj], a_h[i], b_l[jj]);
                #pragma unroll
                for (int jj = 0; jj < 2; jj++)
                    #pragma unroll
                    for (int i = 0; i < 4; i++)
                        mma16(acc[i][jp*2+jj], a_l[i], b_h[jj]);
            }
        }
        __syncthreads();
    }

    const int g = lane >> 2, q = lane & 3;
    const int m0 = blockIdx.y * 128, n0 = blockIdx.x * 128;
    #pragma unroll
    for (int i = 0; i < 4; i++) {
        const int row = m0 + wm * 64 + i * 16 + g;
        #pragma unroll
        for (int j = 0; j < 4; j++) {
            const int colb = n0 + wn * 32 + j * 8;
            if (colb < N) {
                const int col = colb + 2 * q;
                *(float2*)&C[(size_t)row * N + col] =
                    make_float2(acc[i][j][0], acc[i][j][1]);
                *(float2*)&C[(size_t)(row + 8) * N + col] =
                    make_float2(acc[i][j][2], acc[i][j][3]);
            }
        }
    }
}

// ---------------------------------------------------------------------------
__global__ void __launch_bounds__(256) rmsnormA_kernel(
    const float* __restrict__ x, const float* __restrict__ w,
    unsigned* __restrict__ Ph, unsigned* __restrict__ Pl, int ld, int n)
{
    const int row = blockIdx.x;
    const float* xr = x + (size_t)row * ld;
    float s = 0.f;
    for (int i = threadIdx.x; i < n; i += 256) { float v = xr[i]; s += v * v; }
    __shared__ float red[8];
    #pragma unroll
    for (int o = 16; o; o >>= 1) s += __shfl_xor_sync(0xffffffffu, s, o);
    if ((threadIdx.x & 31) == 0) red[threadIdx.x >> 5] = s;
    __syncthreads();
    if (threadIdx.x < 32) {
        float v = (threadIdx.x < 8) ? red[threadIdx.x] : 0.f;
        #pragma unroll
        for (int o = 4; o; o >>= 1) v += __shfl_xor_sync(0xffffffffu, v, o);
        if (threadIdx.x == 0) red[0] = v;
    }
    __syncthreads();
    const float r = rsqrtf(red[0] / (float)n + EPS);
    for (int dp = threadIdx.x; dp < (n >> 1); dp += 256) {
        int d = dp * 2;
        float v0 = w[d] * xr[d] * r, v1 = w[d + 1] * xr[d + 1] * r;
        unsigned hi, lo; split2(v0, v1, hi, lo);
        size_t off = ((size_t)(row >> 4) * (n >> 4) + (d >> 4)) * 128
                   + ((row & 7) * 4 + ((d & 7) >> 1)) * 4
                   + ((d >> 3) & 1) * 2 + ((row >> 3) & 1);
        Ph[off] = hi; Pl[off] = lo;
    }
}

// ---------------------------------------------------------------------------
// Assemble: grid (S_LEN/2, NH); block handles one head, two tokens.
// ---------------------------------------------------------------------------
__global__ void __launch_bounds__(256) assemble_kernel(
    const void* __restrict__ pos_ids)
{
    const int b = blockIdx.x, t0 = 2 * b, tid = threadIdx.x;
    const int h = blockIdx.y;
    __shared__ float cs[2][DR], sn[2][DR], kr[2][DR];
    __shared__ float posv[2];

    if (tid < 2) {
        const int* p32 = (const int*)pos_ids;
        int t = t0 + tid;
        long long pv = (p32[1] == 0) ? ((const long long*)pos_ids)[t]
                                     : (long long)p32[t];
        posv[tid] = (float)pv;
    }
    __syncthreads();
    if (tid < 128) {
        int tok = tid >> 6, i = tid & 63, j = i & 31;
        double e = -((double)(2 * j) / 64.0) * 13.287712379549449;
        float ang = posv[tok] * (float)exp2(e);
        cs[tok][i] = cosf(ang); sn[tok][i] = sinf(ang);
    }
    __syncthreads();
    if (tid < 128) {
        int tok = tid >> 6, i = tid & 63;
        const float* kx = g_kva + (size_t)(t0 + tok) * (KVR + DR) + KVR;
        kr[tok][i] = (i < 32) ? kx[i] * cs[tok][i] - kx[i + 32] * sn[tok][i]
                              : kx[i] * cs[tok][i] + kx[i - 32] * sn[tok][i];
    }
    __syncthreads();

    const float scale = rsqrtf((float)DQK);

    if (tid < 192) {                                  // Q
        int tok = tid / 96, pp = tid % 96, d = 2 * pp;
        int t = t0 + tok;
        const float* qrow = g_q + (size_t)t * (NH * DQK) + h * DQK;
        float v0, v1;
        if (d < DN) { v0 = qrow[d]; v1 = qrow[d + 1]; }
        else {
            int i = d - DN;
            if (i < 32) {
                v0 = qrow[d]   * cs[tok][i]   - qrow[d + 32] * sn[tok][i];
                v1 = qrow[d+1] * cs[tok][i+1] - qrow[d + 33] * sn[tok][i+1];
            } else {
                v0 = qrow[d]   * cs[tok][i]   + qrow[d - 32] * sn[tok][i];
                v1 = qrow[d+1] * cs[tok][i+1] + qrow[d - 31] * sn[tok][i+1];
            }
        }
        v0 *= scale; v1 *= scale;
        unsigned hi, lo; split2(v0, v1, hi, lo);
        int mt = t >> 4, r = t & 15;
        size_t off = ((size_t)(h * 128 + mt) * 12 + (d >> 4)) * 128
                   + ((r & 7) * 4 + ((d & 7) >> 1)) * 4
                   + (((d >> 3) & 1) * 2 + (r >> 3));
        g_Qh[off] = hi; g_Ql[off] = lo;
    }
    if (tid < 192) {                                  // K
        int tok = tid / 96, pp = tid % 96, d = 2 * pp;
        int t = t0 + tok;
        const float* kvrow = g_kvb + (size_t)t * (NH*(DN+DV)) + h * (DN+DV);
        float v0, v1;
        if (d < DN) { v0 = kvrow[d]; v1 = kvrow[d + 1]; }
        else        { v0 = kr[tok][d - DN]; v1 = kr[tok][d - DN + 1]; }
        unsigned hi, lo; split2(v0, v1, hi, lo);
        int nt = t >> 3, n = t & 7;
        size_t off = ((size_t)(h * 256 + nt) * 12 + (d >> 4)) * 64
                   + (n * 4 + ((d & 7) >> 1)) * 2 + ((d >> 3) & 1);
        g_Kh[off] = hi; g_Kl[off] = lo;
    }
    if (tid >= 64 && tid < 192) {                     // V
        int d = tid - 64;
        float v0 = g_kvb[(size_t)t0     * (NH*(DN+DV)) + h*(DN+DV) + DN + d];
        float v1 = g_kvb[(size_t)(t0+1) * (NH*(DN+DV)) + h*(DN+DV) + DN + d];
        unsigned hi, lo; split2(v0, v1, hi, lo);
        size_t off = ((size_t)(h * 128 + (t0 >> 4)) * 16 + (d >> 3)) * 64
                   + ((d & 7) * 4 + ((t0 & 7) >> 1)) * 2 + ((t0 >> 3) & 1);
        g_Vh[off] = hi; g_Vl[off] = lo;
    }
}

// ---------------------------------------------------------------------------
// Flash attention: QH in regs, QL in smem, K/V cp.async double-buffered.
// ---------------------------------------------------------------------------
constexpr int FL_STAGE = 20480;  // u32 per stage (KH 6144, KL 6144, VH 4096, VL 4096)
constexpr size_t FLASH_SMEM_BYTES = (12288 + 2 * FL_STAGE) * 4;  // 212992

__global__ void __launch_bounds__(256) flash_kernel()
{
    const int bx = blockIdx.x;
    const int qt = 15 - (bx >> 4);
    const int h  = bx & 15;
    const int q0 = qt * 128;
    const int tid = threadIdx.x, wid = tid >> 5, lane = tid & 31;
    const int g = lane >> 2, q = lane & 3;

    extern __shared__ unsigned smu[];
    unsigned* QL = smu;
    const uint32_t sb = (uint32_t)__cvta_generic_to_shared(smu);

    uint4 qh[12];
    {
        const size_t qbase = (size_t)(h * 128 + qt * 8 + wid) * 12 * 128;
        #pragma unroll
        for (int kt = 0; kt < 12; kt++)
            qh[kt] = *(const uint4*)&g_Qh[qbase + kt * 128 + lane * 4];
        const uint4* gl = (const uint4*)(g_Ql + (size_t)(h * 128 + qt * 8) * 1536);
        uint4* dl = (uint4*)QL;
        #pragma unroll
        for (int j = 0; j < 12; j++) dl[j * 256 + tid] = gl[j * 256 + tid];
    }

    const int niter = 2 * (qt + 1);
    const int wrow0 = q0 + wid * 16;

    auto issue = [&](int it, int st) {
        const uint4* gkh = (const uint4*)(g_Kh + (size_t)(h * 256 + it * 8) * 768);
        const uint4* gkl = (const uint4*)(g_Kl + (size_t)(h * 256 + it * 8) * 768);
        const uint4* gvh = (const uint4*)(g_Vh + (size_t)(h * 128 + it * 4) * 1024);
        const uint4* gvl = (const uint4*)(g_Vl + (size_t)(h * 128 + it * 4) * 1024);
        const uint32_t s0 = sb + (12288u + (uint32_t)st * FL_STAGE) * 4;
        #pragma unroll
        for (int j = 0; j < 6; j++) {
            cpa16(s0 +         (j * 256 + tid) * 16, gkh + j * 256 + tid);
            cpa16(s0 + 24576 + (j * 256 + tid) * 16, gkl + j * 256 + tid);
        }
        #pragma unroll
        for (int j = 0; j < 4; j++) {
            cpa16(s0 + 49152 + (j * 256 + tid) * 16, gvh + j * 256 + tid);
            cpa16(s0 + 65536 + (j * 256 + tid) * 16, gvl + j * 256 + tid);
        }
        asm volatile("cp.async.commit_group;" ::: "memory");
    };

    float O[16][4];
    #pragma unroll
    for (int nt = 0; nt < 16; nt++)
        #pragma unroll
        for (int r = 0; r < 4; r++) O[nt][r] = 0.f;
    float m0 = -1e30f, m1 = -1e30f, l0 = 0.f, l1 = 0.f;

    issue(0, 0);

    for (int it = 0; it < niter; it++) {
        const int s = it & 1;
        const int k0 = it * 64;
        if (it + 1 < niter) {
            issue(it + 1, s ^ 1);
            asm volatile("cp.async.wait_group 1;" ::: "memory");
        } else {
            asm volatile("cp.async.wait_group 0;" ::: "memory");
        }
        __syncthreads();

        unsigned* KHs = smu + 12288 + s * FL_STAGE;
        unsigned* KLs = KHs + 6144;
        unsigned* VHs = KHs + 12288;
        unsigned* VLs = KHs + 16384;

        if (k0 <= wrow0 + 15) {
            float S[8][4];
            #pragma unroll
            for (int nt = 0; nt < 8; nt++)
                #pragma unroll
                for (int r = 0; r < 4; r++) S[nt][r] = 0.f;

            #pragma unroll
            for (int kt = 0; kt < 12; kt++) {
                uint4 qhv = qh[kt];
                uint4 qlv = *(const uint4*)&QL[wid * 1536 + kt * 128 + lane * 4];
                #pragma unroll
                for (int nt = 0; nt < 8; nt++) {
                    uint2 kh = *(const uint2*)&KHs[(nt * 12 + kt) * 64 + lane * 2];
                    uint2 kl = *(const uint2*)&KLs[(nt * 12 + kt) * 64 + lane * 2];
                    mma16(S[nt], qhv, kh);
                    mma16(S[nt], qhv, kl);
                    mma16(S[nt], qlv, kh);
                }
            }

            if (k0 + 63 > wrow0) {
                const int row0 = wrow0 + g, row1 = row0 + 8;
                #pragma unroll
                for (int nt = 0; nt < 8; nt++) {
                    int col = k0 + nt * 8 + 2 * q;
                    if (col     > row0) S[nt][0] = -1e30f;
                    if (col + 1 > row0) S[nt][1] = -1e30f;
                    if (col     > row1) S[nt][2] = -1e30f;
                    if (col + 1 > row1) S[nt][3] = -1e30f;
                }
            }

            float rm0 = -1e30f, rm1 = -1e30f;
            #pragma unroll
            for (int nt = 0; nt < 8; nt++) {
                rm0 = fmaxf(rm0, fmaxf(S[nt][0], S[nt][1]));
                rm1 = fmaxf(rm1, fmaxf(S[nt][2], S[nt][3]));
            }
            rm0 = fmaxf(rm0, __shfl_xor_sync(0xffffffffu, rm0, 1));
            rm0 = fmaxf(rm0, __shfl_xor_sync(0xffffffffu, rm0, 2));
            rm1 = fmaxf(rm1, __shfl_xor_sync(0xffffffffu, rm1, 1));
            rm1 = fmaxf(rm1, __shfl_xor_sync(0xffffffffu, rm1, 2));

            float mn0 = fmaxf(m0, rm0), mn1 = fmaxf(m1, rm1);
            float a0 = __expf(m0 - mn0), a1 = __expf(m1 - mn1);

            unsigned PH[8], PL[8], P8H[8], P8L[8];
            float s0 = 0.f, s1 = 0.f;
            #pragma unroll
            for (int nt = 0; nt < 8; nt++) {
                float p00 = __expf(S[nt][0] - mn0);
                float p01 = __expf(S[nt][1] - mn0);
                float p10 = __expf(S[nt][2] - mn1);
                float p11 = __expf(S[nt][3] - mn1);
                s0 += p00 + p01; s1 += p10 + p11;
                split2(p00, p01, PH[nt], PL[nt]);
                split2(p10, p11, P8H[nt], P8L[nt]);
            }
            s0 += __shfl_xor_sync(0xffffffffu, s0, 1);
            s0 += __shfl_xor_sync(0xffffffffu, s0, 2);
            s1 += __shfl_xor_sync(0xffffffffu, s1, 1);
            s1 += __shfl_xor_sync(0xffffffffu, s1, 2);

            l0 = l0 * a0 + s0; l1 = l1 * a1 + s1;
            m0 = mn0; m1 = mn1;

            #pragma unroll
            for (int nt = 0; nt < 16; nt++) {
                O[nt][0] *= a0; O[nt][1] *= a0;
                O[nt][2] *= a1; O[nt][3] *= a1;
            }

            #pragma unroll
            for (int kt2 = 0; kt2 < 4; kt2++) {
                uint4 ah = make_uint4(PH[2*kt2], P8H[2*kt2], PH[2*kt2+1], P8H[2*kt2+1]);
                uint4 al = make_uint4(PL[2*kt2], P8L[2*kt2], PL[2*kt2+1], P8L[2*kt2+1]);
                #pragma unroll
                for (int nt = 0; nt < 16; nt++) {
                    uint2 vh = *(const uint2*)&VHs[(kt2 * 16 + nt) * 64 + lane * 2];
                    uint2 vl = *(const uint2*)&VLs[(kt2 * 16 + nt) * 64 + lane * 2];
                    mma16(O[nt], ah, vh);
                    mma16(O[nt], ah, vl);
                    mma16(O[nt], al, vh);
                }
            }
        }
        __syncthreads();
    }

    const float inv0 = __fdividef(1.f, l0), inv1 = __fdividef(1.f, l1);
    const int row0 = wrow0 + g;
    const size_t baseRow = (size_t)(row0 >> 4) * 128;
    #pragma unroll
    for (int nt = 0; nt < 16; nt++) {
        const int ktv = h * 8 + (nt >> 1);
        const size_t off = (baseRow + ktv) * 128 + lane * 4 + (nt & 1) * 2;
        unsigned hi, lo;
        split2(O[nt][0] * inv0, O[nt][1] * inv0, hi, lo);
        g_AatH[off] = hi; g_AatL[off] = lo;
        split2(O[nt][2] * inv1, O[nt][3] * inv1, hi, lo);
        g_AatH[off + 1] = hi; g_AatL[off + 1] = lo;
    }
}

// ---------------------------------------------------------------------------
extern "C" void kernel_launch(void* const* d_in, const int* in_sizes, int n_in,
                              void* d_out, int out_size)
{
    const float* hs       = (const float*)d_in[0];
    const void*  pos_ids  = d_in[1];
    const float* q_a_w    = (const float*)d_in[2];
    const float* q_a_ln_w = (const float*)d_in[3];
    const float* q_b_w    = (const float*)d_in[4];
    const float* kv_a_w   = (const float*)d_in[5];
    const float* kv_a_ln_w= (const float*)d_in[6];
    const float* kv_b_w   = (const float*)d_in[7];
    const float* o_w      = (const float*)d_in[8];
    float*       out      = (float*)d_out;

    float *p_qa, *p_q, *p_kva, *p_kvb;
    cudaGetSymbolAddress((void**)&p_qa,  g_qa);
    cudaGetSymbolAddress((void**)&p_q,   g_q);
    cudaGetSymbolAddress((void**)&p_kva, g_kva);
    cudaGetSymbolAddress((void**)&p_kvb, g_kvb);
    unsigned *AhsH,*AhsL,*AqaH,*AqaL,*AkvH,*AkvL,*AatH,*AatL;
    unsigned *BqaH,*BqaL,*BqbH,*BqbL,*BkaH,*BkaL,*BkbH,*BkbL,*BowH,*BowL;
    cudaGetSymbolAddress((void**)&AhsH, g_AhsH); cudaGetSymbolAddress((void**)&AhsL, g_AhsL);
    cudaGetSymbolAddress((void**)&AqaH, g_AqaH); cudaGetSymbolAddress((void**)&AqaL, g_AqaL);
    cudaGetSymbolAddress((void**)&AkvH, g_AkvH); cudaGetSymbolAddress((void**)&AkvL, g_AkvL);
    cudaGetSymbolAddress((void**)&AatH, g_AatH); cudaGetSymbolAddress((void**)&AatL, g_AatL);
    cudaGetSymbolAddress((void**)&BqaH, g_BqaH); cudaGetSymbolAddress((void**)&BqaL, g_BqaL);
    cudaGetSymbolAddress((void**)&BqbH, g_BqbH); cudaGetSymbolAddress((void**)&BqbL, g_BqbL);
    cudaGetSymbolAddress((void**)&BkaH, g_BkaH); cudaGetSymbolAddress((void**)&BkaL, g_BkaL);
    cudaGetSymbolAddress((void**)&BkbH, g_BkbH); cudaGetSymbolAddress((void**)&BkbL, g_BkbL);
    cudaGetSymbolAddress((void**)&BowH, g_BowH); cudaGetSymbolAddress((void**)&BowL, g_BowL);

    cudaFuncSetAttribute(flash_kernel,
                         cudaFuncAttributeMaxDynamicSharedMemorySize,
                         (int)FLASH_SMEM_BYTES);

    static cudaStream_t sA = nullptr, sB = nullptr;
    static cudaEvent_t evRoot, evA, evW, evKV;
    if (!sA) {
        cudaStreamCreateWithFlags(&sA, cudaStreamNonBlocking);
        cudaStreamCreateWithFlags(&sB, cudaStreamNonBlocking);
        cudaEventCreateWithFlags(&evRoot, cudaEventDisableTiming);
        cudaEventCreateWithFlags(&evA, cudaEventDisableTiming);
        cudaEventCreateWithFlags(&evW, cudaEventDisableTiming);
        cudaEventCreateWithFlags(&evKV, cudaEventDisableTiming);
    }

    // fork
    cudaEventRecord(evRoot, 0);
    cudaStreamWaitEvent(sA, evRoot, 0);
    cudaStreamWaitEvent(sB, evRoot, 0);

    // main stream: q chain
    convB_kernel<<<6144, 256>>>(q_a_w, BqaH, BqaL, QR, HID);
    convA_kernel<<<8192, 256>>>(hs, AhsH, AhsL, HID);
    cudaEventRecord(evA, 0);
    gemm_fr_kernel<<<dim3(12, 16), 256>>>(AhsH, AhsL, BqaH, BqaL, p_qa, QR, HID);
    rmsnormA_kernel<<<S_LEN, 256>>>(p_qa, q_a_ln_w, AqaH, AqaL, QR, QR);

    // sA: kv chain
    convB_kernel<<<2560, 256, 0, sA>>>(kv_a_w, BkaH, BkaL, KVR + DR, HID);
    convB_kernel<<<4096, 256, 0, sA>>>(kv_b_w, BkbH, BkbL, NH * (DN + DV), KVR);
    cudaStreamWaitEvent(sA, evA, 0);
    gemm_fr_kernel<<<dim3(5, 16), 256, 0, sA>>>(AhsH, AhsL, BkaH, BkaL, p_kva,
                                                KVR + DR, HID);
    rmsnormA_kernel<<<S_LEN, 256, 0, sA>>>(p_kva, kv_a_ln_w, AkvH, AkvL,
                                           KVR + DR, KVR);
    gemm_fr_kernel<<<dim3(32, 16), 256, 0, sA>>>(AkvH, AkvL, BkbH, BkbL, p_kvb,
                                                 NH * (DN + DV), KVR);
    cudaEventRecord(evKV, sA);

    // sB: remaining weight conversions
    convB_kernel<<<9216, 256, 0, sB>>>(q_b_w, BqbH, BqbL, NH * DQK, QR);
    convB_kernel<<<8192, 256, 0, sB>>>(o_w, BowH, BowL, HID, HID);
    cudaEventRecord(evW, sB);

    // join and finish on main stream
    cudaStreamWaitEvent(0, evW, 0);
    gemm_fr_kernel<<<dim3(24, 16), 256>>>(AqaH, AqaL, BqbH, BqbL, p_q, NH * DQK, QR);
    cudaStreamWaitEvent(0, evKV, 0);
    assemble_kernel<<<dim3(S_LEN / 2, NH), 256>>>(pos_ids);
    flash_kernel<<<256, 256, FLASH_SMEM_BYTES>>>();
    gemm_fr_kernel<<<dim3(16, 16), 256>>>(AatH, AatL, BowH, BowL, out, HID, HID);
}